// round 1
// baseline (speedup 1.0000x reference)
#include <cuda_runtime.h>
#include <math.h>

#define N_ATOMS 100000
#define N_EDGES 3200000
#define N_MOL   2000
#define HID     64
#define NGAUSS  50
#define NLAYERS 3
#define TBL_T   4096
#define DMAX    8.6603f           /* >= 5*sqrt(3) = 8.66025 */
#define TBL_SCALE ((float)(TBL_T-1) / DMAX)
#define LOG2F_  0.69314718055994530942f
#define PI_OVER_CUTOFF 0.31415926535897932385f
#define BM 128

/* ------------------------- scratch (no allocs allowed) ------------------ */
__device__ float              g_d[N_EDGES];
__device__ int                g_hist[N_ATOMS];
__device__ int                g_row[N_ATOMS + 1];
__device__ int                g_cur[N_ATOMS];
__device__ unsigned long long g_edata[N_EDGES];
__device__ float              g_table[NLAYERS * TBL_T * HID];
__device__ float              g_h[(size_t)N_ATOMS * HID];
__device__ float              g_x[(size_t)N_ATOMS * HID];
__device__ float              g_agg[(size_t)N_ATOMS * HID];
__device__ float              g_molsum[N_MOL];

__device__ __forceinline__ float ssp(float v) {
    /* softplus(v) - log(2), numerically stable (matches jnp.logaddexp(v,0)) */
    return fmaxf(v, 0.0f) + log1pf(expf(-fabsf(v))) - LOG2F_;
}

/* ------------------------- zero hist + molsum --------------------------- */
__global__ void zero_kernel() {
    int i = blockIdx.x * blockDim.x + threadIdx.x;
    if (i < N_ATOMS) g_hist[i] = 0;
    if (i < N_MOL)   g_molsum[i] = 0.0f;
}

/* --------------- build W_l(d) lookup table: [L][T][64] ------------------ */
__global__ void table_kernel(const float* __restrict__ w1, const float* __restrict__ b1,
                             const float* __restrict__ w2, const float* __restrict__ b2) {
    int l = blockIdx.x / TBL_T;
    int t = blockIdx.x % TBL_T;
    int j = threadIdx.x;                       /* 64 threads */
    float d = (float)t * (DMAX / (float)(TBL_T - 1));

    __shared__ float rbf[NGAUSS];
    __shared__ float tmp[HID];

    if (j < NGAUSS) {
        float off = (float)j * (10.0f / 49.0f);
        float u = d - off;
        const float coeff = -0.5f * (49.0f / 10.0f) * (49.0f / 10.0f);
        rbf[j] = expf(coeff * u * u);
    }
    __syncthreads();

    float acc = b1[l * HID + j];
    const float* W1 = w1 + (size_t)l * NGAUSS * HID;
#pragma unroll
    for (int k = 0; k < NGAUSS; k++) acc = fmaf(rbf[k], W1[k * HID + j], acc);
    tmp[j] = ssp(acc);
    __syncthreads();

    float acc2 = b2[l * HID + j];
    const float* W2 = w2 + (size_t)l * HID * HID;
#pragma unroll
    for (int k = 0; k < HID; k++) acc2 = fmaf(tmp[k], W2[k * HID + j], acc2);

    float C = 0.5f * (cosf(d * PI_OVER_CUTOFF) + 1.0f);
    g_table[((size_t)l * TBL_T + t) * HID + j] = acc2 * C;
}

/* --------------- per-edge distance + dst histogram ---------------------- */
__global__ void dist_hist_kernel(const int* __restrict__ ei, const float* __restrict__ pos) {
    int e = blockIdx.x * blockDim.x + threadIdx.x;
    if (e >= N_EDGES) return;
    int s = ei[e];
    int t = ei[N_EDGES + e];
    float dx = pos[s * 3 + 0] - pos[t * 3 + 0];
    float dy = pos[s * 3 + 1] - pos[t * 3 + 1];
    float dz = pos[s * 3 + 2] - pos[t * 3 + 2];
    float d = sqrtf(dx * dx + dy * dy + dz * dz);
    g_d[e] = d;
    atomicAdd(&g_hist[t], 1);
}

/* --------------- single-block exclusive scan of hist -------------------- */
__global__ void scan_kernel() {
    __shared__ int wsum[32];
    int tid = threadIdx.x;                 /* 1024 threads */
    int lane = tid & 31, wid = tid >> 5;
    int carry = 0;
    for (int base = 0; base < N_ATOMS; base += 4096) {
        int idx = base + tid * 4;
        int v0 = (idx + 0 < N_ATOMS) ? g_hist[idx + 0] : 0;
        int v1 = (idx + 1 < N_ATOMS) ? g_hist[idx + 1] : 0;
        int v2 = (idx + 2 < N_ATOMS) ? g_hist[idx + 2] : 0;
        int v3 = (idx + 3 < N_ATOMS) ? g_hist[idx + 3] : 0;
        int s1 = v0 + v1, s2 = s1 + v2, s3 = s2 + v3;
        int ts = s3;
        int si = ts;
#pragma unroll
        for (int o = 1; o < 32; o <<= 1) {
            int u = __shfl_up_sync(0xffffffffu, si, o);
            if (lane >= o) si += u;
        }
        if (lane == 31) wsum[wid] = si;
        __syncthreads();
        if (wid == 0) {
            int w = wsum[lane];
#pragma unroll
            for (int o = 1; o < 32; o <<= 1) {
                int u = __shfl_up_sync(0xffffffffu, w, o);
                if (lane >= o) w += u;
            }
            wsum[lane] = w;
        }
        __syncthreads();
        int woff = (wid > 0) ? wsum[wid - 1] : 0;
        int excl = carry + woff + (si - ts);
        if (idx + 0 < N_ATOMS) { g_row[idx + 0] = excl;      g_cur[idx + 0] = excl; }
        if (idx + 1 < N_ATOMS) { g_row[idx + 1] = excl + v0; g_cur[idx + 1] = excl + v0; }
        if (idx + 2 < N_ATOMS) { g_row[idx + 2] = excl + s1; g_cur[idx + 2] = excl + s1; }
        if (idx + 3 < N_ATOMS) { g_row[idx + 3] = excl + s2; g_cur[idx + 3] = excl + s2; }
        carry += wsum[31];
        __syncthreads();
    }
    if (tid == 0) g_row[N_ATOMS] = carry;
}

/* --------------- scatter edges into dst-sorted order -------------------- */
__global__ void scatter_kernel(const int* __restrict__ ei) {
    int e = blockIdx.x * blockDim.x + threadIdx.x;
    if (e >= N_EDGES) return;
    int s = ei[e];
    int t = ei[N_EDGES + e];
    int p = atomicAdd(&g_cur[t], 1);
    unsigned int db = __float_as_uint(g_d[e]);
    g_edata[p] = ((unsigned long long)db << 32) | (unsigned int)s;
}

/* --------------- h = emb[z] --------------------------------------------- */
__global__ void hinit_kernel(const int* __restrict__ z, const float* __restrict__ emb) {
    int i = blockIdx.x * blockDim.x + threadIdx.x;
    if (i >= N_ATOMS * HID) return;
    int n = i >> 6, j = i & 63;
    g_h[i] = emb[z[n] * HID + j];
}

/* --------------- shared 64x64 GEMM micro-tile ---------------------------- */
__device__ __forceinline__ void gemm_tile(const float (*As)[HID], const float (*Ws)[HID],
                                          int tx, int ty, float acc[4][8]) {
#pragma unroll 2
    for (int k4 = 0; k4 < HID; k4 += 4) {
        float4 a[4];
#pragma unroll
        for (int r = 0; r < 4; r++) a[r] = *(const float4*)&As[4 * ty + r][k4];
#pragma unroll
        for (int kk = 0; kk < 4; kk++) {
            float4 w0 = *(const float4*)&Ws[k4 + kk][8 * tx];
            float4 w1 = *(const float4*)&Ws[k4 + kk][8 * tx + 4];
#pragma unroll
            for (int r = 0; r < 4; r++) {
                float av = ((const float*)&a[r])[kk];
                acc[r][0] = fmaf(av, w0.x, acc[r][0]);
                acc[r][1] = fmaf(av, w0.y, acc[r][1]);
                acc[r][2] = fmaf(av, w0.z, acc[r][2]);
                acc[r][3] = fmaf(av, w0.w, acc[r][3]);
                acc[r][4] = fmaf(av, w1.x, acc[r][4]);
                acc[r][5] = fmaf(av, w1.y, acc[r][5]);
                acc[r][6] = fmaf(av, w1.z, acc[r][6]);
                acc[r][7] = fmaf(av, w1.w, acc[r][7]);
            }
        }
    }
}

/* --------------- x = h @ cf_lin1_w (no bias) ----------------------------- */
__global__ void __launch_bounds__(256) dense_x_kernel(const float* __restrict__ W) {
    __shared__ float As[BM][HID];
    __shared__ float Ws[HID][HID];
    int tid = threadIdx.x;
    int r0 = blockIdx.x * BM;

    for (int i = tid; i < HID * HID / 4; i += 256)
        ((float4*)Ws)[i] = ((const float4*)W)[i];
#pragma unroll
    for (int i = 0; i < 8; i++) {
        int flat = i * 1024 + tid * 4;
        int row = flat >> 6, k = flat & 63;
        int gr = r0 + row;
        float4 v = make_float4(0.f, 0.f, 0.f, 0.f);
        if (gr < N_ATOMS) v = *(const float4*)(g_h + (size_t)gr * HID + k);
        *(float4*)&As[row][k] = v;
    }
    __syncthreads();

    int tx = tid & 7, ty = tid >> 3;
    float acc[4][8];
#pragma unroll
    for (int r = 0; r < 4; r++)
#pragma unroll
        for (int c = 0; c < 8; c++) acc[r][c] = 0.0f;

    gemm_tile(As, Ws, tx, ty, acc);

#pragma unroll
    for (int r = 0; r < 4; r++) {
        int gr = r0 + 4 * ty + r;
        if (gr < N_ATOMS) {
            *(float4*)(g_x + (size_t)gr * HID + 8 * tx) =
                make_float4(acc[r][0], acc[r][1], acc[r][2], acc[r][3]);
            *(float4*)(g_x + (size_t)gr * HID + 8 * tx + 4) =
                make_float4(acc[r][4], acc[r][5], acc[r][6], acc[r][7]);
        }
    }
}

/* --------------- message + segment-sum (one warp per dst node) ----------- */
__global__ void aggregate_kernel(int layer) {
    int warp = (blockIdx.x * blockDim.x + threadIdx.x) >> 5;
    int lane = threadIdx.x & 31;
    if (warp >= N_ATOMS) return;

    const float* tab = g_table + (size_t)layer * TBL_T * HID;
    int beg = g_row[warp];
    int end = g_row[warp + 1];
    int ch = lane * 2;

    float accx = 0.0f, accy = 0.0f;
    for (int base = beg; base < end; base += 32) {
        int cnt = min(32, end - base);
        unsigned long long pk = (lane < cnt) ? g_edata[base + lane] : 0ull;
        for (int j = 0; j < cnt; j++) {
            unsigned long long p = __shfl_sync(0xffffffffu, pk, j);
            int s = (int)(unsigned int)(p & 0xffffffffull);
            float d = __uint_as_float((unsigned int)(p >> 32));
            float ft = d * TBL_SCALE;
            int t = (int)ft;
            t = min(t, TBL_T - 2);
            float f = ft - (float)t;
            const float* row = tab + (size_t)t * HID + ch;
            float2 w0 = *(const float2*)row;
            float2 w1 = *(const float2*)(row + HID);
            float2 xv = *(const float2*)(g_x + (size_t)s * HID + ch);
            float wa = fmaf(f, w1.x - w0.x, w0.x);
            float wb = fmaf(f, w1.y - w0.y, w0.y);
            accx = fmaf(xv.x, wa, accx);
            accy = fmaf(xv.y, wb, accy);
        }
    }
    *(float2*)(g_agg + (size_t)warp * HID + ch) = make_float2(accx, accy);
}

/* --------- h += ( ssp(agg@W1 + b1) @ W2 + b2 )  (fused post block) ------- */
__global__ void __launch_bounds__(256) dense_post_kernel(const float* __restrict__ W1,
                                                         const float* __restrict__ b1,
                                                         const float* __restrict__ W2,
                                                         const float* __restrict__ b2) {
    __shared__ float As[BM][HID];
    __shared__ float Ws[HID][HID];
    int tid = threadIdx.x;
    int r0 = blockIdx.x * BM;

    for (int i = tid; i < HID * HID / 4; i += 256)
        ((float4*)Ws)[i] = ((const float4*)W1)[i];
#pragma unroll
    for (int i = 0; i < 8; i++) {
        int flat = i * 1024 + tid * 4;
        int row = flat >> 6, k = flat & 63;
        int gr = r0 + row;
        float4 v = make_float4(0.f, 0.f, 0.f, 0.f);
        if (gr < N_ATOMS) v = *(const float4*)(g_agg + (size_t)gr * HID + k);
        *(float4*)&As[row][k] = v;
    }
    __syncthreads();

    int tx = tid & 7, ty = tid >> 3;
    float acc[4][8];
#pragma unroll
    for (int r = 0; r < 4; r++)
#pragma unroll
        for (int c = 0; c < 8; c++) acc[r][c] = 0.0f;

    gemm_tile(As, Ws, tx, ty, acc);
    __syncthreads();   /* everyone done reading As/Ws of GEMM1 */

    float4 bb0 = *(const float4*)&b1[8 * tx];
    float4 bb1 = *(const float4*)&b1[8 * tx + 4];
#pragma unroll
    for (int r = 0; r < 4; r++) {
        float t0 = ssp(acc[r][0] + bb0.x);
        float t1 = ssp(acc[r][1] + bb0.y);
        float t2 = ssp(acc[r][2] + bb0.z);
        float t3 = ssp(acc[r][3] + bb0.w);
        float t4 = ssp(acc[r][4] + bb1.x);
        float t5 = ssp(acc[r][5] + bb1.y);
        float t6 = ssp(acc[r][6] + bb1.z);
        float t7 = ssp(acc[r][7] + bb1.w);
        *(float4*)&As[4 * ty + r][8 * tx]     = make_float4(t0, t1, t2, t3);
        *(float4*)&As[4 * ty + r][8 * tx + 4] = make_float4(t4, t5, t6, t7);
    }
    for (int i = tid; i < HID * HID / 4; i += 256)
        ((float4*)Ws)[i] = ((const float4*)W2)[i];
    __syncthreads();

#pragma unroll
    for (int r = 0; r < 4; r++)
#pragma unroll
        for (int c = 0; c < 8; c++) acc[r][c] = 0.0f;

    gemm_tile(As, Ws, tx, ty, acc);

    float4 cb0 = *(const float4*)&b2[8 * tx];
    float4 cb1 = *(const float4*)&b2[8 * tx + 4];
#pragma unroll
    for (int r = 0; r < 4; r++) {
        int gr = r0 + 4 * ty + r;
        if (gr < N_ATOMS) {
            float* hp = g_h + (size_t)gr * HID + 8 * tx;
            float4 h0 = *(float4*)hp;
            float4 h1 = *(float4*)(hp + 4);
            h0.x += acc[r][0] + cb0.x;  h0.y += acc[r][1] + cb0.y;
            h0.z += acc[r][2] + cb0.z;  h0.w += acc[r][3] + cb0.w;
            h1.x += acc[r][4] + cb1.x;  h1.y += acc[r][5] + cb1.y;
            h1.z += acc[r][6] + cb1.z;  h1.w += acc[r][7] + cb1.w;
            *(float4*)hp       = h0;
            *(float4*)(hp + 4) = h1;
        }
    }
}

/* --------------- readout: per-atom MLP (64->32->1) + molecule sum -------- */
__global__ void readout_kernel(const int* __restrict__ batch,
                               const float* __restrict__ w1, const float* __restrict__ b1,
                               const float* __restrict__ w2, const float* __restrict__ b2) {
    int warp = (blockIdx.x * blockDim.x + threadIdx.x) >> 5;
    int lane = threadIdx.x & 31;
    if (warp >= N_ATOMS) return;

    float h0 = g_h[(size_t)warp * HID + lane];
    float h1 = g_h[(size_t)warp * HID + 32 + lane];

    float acc = b1[lane];
#pragma unroll
    for (int k = 0; k < 32; k++) {
        float hk = __shfl_sync(0xffffffffu, h0, k);
        acc = fmaf(hk, w1[k * 32 + lane], acc);
    }
#pragma unroll
    for (int k = 0; k < 32; k++) {
        float hk = __shfl_sync(0xffffffffu, h1, k);
        acc = fmaf(hk, w1[(32 + k) * 32 + lane], acc);
    }
    float t = ssp(acc) * w2[lane];
#pragma unroll
    for (int o = 16; o > 0; o >>= 1) t += __shfl_xor_sync(0xffffffffu, t, o);
    if (lane == 0) atomicAdd(&g_molsum[batch[warp]], t + b2[0]);
}

/* --------------- out[g] = molsum[g]*fin_w + fin_b ------------------------ */
__global__ void final_kernel(const float* __restrict__ fw, const float* __restrict__ fb,
                             float* __restrict__ out) {
    int g = blockIdx.x * blockDim.x + threadIdx.x;
    if (g < N_MOL) out[g] = g_molsum[g] * fw[0] + fb[0];
}

/* ========================================================================= */
extern "C" void kernel_launch(void* const* d_in, const int* in_sizes, int n_in,
                              void* d_out, int out_size) {
    const int*   z      = (const int*)d_in[0];
    const float* pos    = (const float*)d_in[1];
    const int*   batch  = (const int*)d_in[2];
    const int*   ei     = (const int*)d_in[3];
    const float* emb    = (const float*)d_in[4];
    const float* out_w1 = (const float*)d_in[5];
    const float* out_b1 = (const float*)d_in[6];
    const float* out_w2 = (const float*)d_in[7];
    const float* out_b2 = (const float*)d_in[8];
    const float* fin_w  = (const float*)d_in[9];
    const float* fin_b  = (const float*)d_in[10];
    const float* mlp_w1 = (const float*)d_in[11];
    const float* mlp_b1 = (const float*)d_in[12];
    const float* mlp_w2 = (const float*)d_in[13];
    const float* mlp_b2 = (const float*)d_in[14];
    const float* cf1    = (const float*)d_in[15];
    const float* cf2    = (const float*)d_in[16];
    const float* cf2b   = (const float*)d_in[17];
    const float* intw   = (const float*)d_in[18];
    const float* intb   = (const float*)d_in[19];

    (void)in_sizes; (void)n_in; (void)out_size;

    zero_kernel<<<(N_ATOMS + 255) / 256, 256>>>();
    table_kernel<<<NLAYERS * TBL_T, 64>>>(mlp_w1, mlp_b1, mlp_w2, mlp_b2);
    dist_hist_kernel<<<(N_EDGES + 255) / 256, 256>>>(ei, pos);
    scan_kernel<<<1, 1024>>>();
    scatter_kernel<<<(N_EDGES + 255) / 256, 256>>>(ei);
    hinit_kernel<<<(N_ATOMS * HID + 255) / 256, 256>>>(z, emb);

    int gemm_blocks = (N_ATOMS + BM - 1) / BM;
    int warp_blocks = (N_ATOMS * 32 + 255) / 256;

    for (int l = 0; l < NLAYERS; l++) {
        dense_x_kernel<<<gemm_blocks, 256>>>(cf1 + (size_t)l * HID * HID);
        aggregate_kernel<<<warp_blocks, 256>>>(l);
        dense_post_kernel<<<gemm_blocks, 256>>>(cf2 + (size_t)l * HID * HID,
                                                cf2b + (size_t)l * HID,
                                                intw + (size_t)l * HID * HID,
                                                intb + (size_t)l * HID);
    }

    readout_kernel<<<warp_blocks, 256>>>(batch, out_w1, out_b1, out_w2, out_b2);
    final_kernel<<<(N_MOL + 255) / 256, 256>>>(fin_w, fin_b, (float*)d_out);
}

// round 2
// speedup vs baseline: 1.2127x; 1.2127x over previous
#include <cuda_runtime.h>
#include <cuda_fp16.h>
#include <math.h>

#define N_ATOMS 100000
#define N_EDGES 3200000
#define N_MOL   2000
#define HID     64
#define NGAUSS  50
#define NLAYERS 3
#define TBL_T   2048
#define DMAX    8.6603f           /* >= 5*sqrt(3) = 8.66025 */
#define TBL_SCALE ((float)(TBL_T-1) / DMAX)
#define LOG2F_  0.69314718055994530942f
#define PI_OVER_CUTOFF 0.31415926535897932385f
#define BM 128
#define SCAN_BLK 98               /* ceil(100000/1024) */

/* ------------------------- scratch (no allocs allowed) ------------------ */
__device__ int                g_hist[N_ATOMS];
__device__ int                g_row[N_ATOMS + 1];
__device__ int                g_cur[N_ATOMS];
__device__ int                g_part[128];
__device__ unsigned long long g_edata[N_EDGES];
__device__ __align__(16) __half g_table[NLAYERS * TBL_T * HID];
__device__ float              g_h[(size_t)N_ATOMS * HID];
__device__ __align__(16) __half g_x[(size_t)N_ATOMS * HID];
__device__ float              g_agg[(size_t)N_ATOMS * HID];
__device__ float              g_molsum[N_MOL];

__device__ __forceinline__ float ssp(float v) {
    return fmaxf(v, 0.0f) + log1pf(expf(-fabsf(v))) - LOG2F_;
}

/* ------------------------- zero hist + molsum --------------------------- */
__global__ void zero_kernel() {
    int i = blockIdx.x * blockDim.x + threadIdx.x;
    if (i < N_ATOMS) g_hist[i] = 0;
    if (i < N_MOL)   g_molsum[i] = 0.0f;
}

/* --------------- build W_l(d) lookup table (fp16): [L][T][64] ----------- */
__global__ void table_kernel(const float* __restrict__ w1, const float* __restrict__ b1,
                             const float* __restrict__ w2, const float* __restrict__ b2) {
    int l = blockIdx.x / TBL_T;
    int t = blockIdx.x % TBL_T;
    int j = threadIdx.x;                       /* 64 threads */
    float d = (float)t * (DMAX / (float)(TBL_T - 1));

    __shared__ float rbf[NGAUSS];
    __shared__ float tmp[HID];

    if (j < NGAUSS) {
        float off = (float)j * (10.0f / 49.0f);
        float u = d - off;
        const float coeff = -0.5f * (49.0f / 10.0f) * (49.0f / 10.0f);
        rbf[j] = expf(coeff * u * u);
    }
    __syncthreads();

    float acc = b1[l * HID + j];
    const float* W1 = w1 + (size_t)l * NGAUSS * HID;
#pragma unroll
    for (int k = 0; k < NGAUSS; k++) acc = fmaf(rbf[k], W1[k * HID + j], acc);
    tmp[j] = ssp(acc);
    __syncthreads();

    float acc2 = b2[l * HID + j];
    const float* W2 = w2 + (size_t)l * HID * HID;
#pragma unroll
    for (int k = 0; k < HID; k++) acc2 = fmaf(tmp[k], W2[k * HID + j], acc2);

    float C = 0.5f * (cosf(d * PI_OVER_CUTOFF) + 1.0f);
    g_table[((size_t)l * TBL_T + t) * HID + j] = __float2half_rn(acc2 * C);
}

/* --------------- dst histogram ------------------------------------------ */
__global__ void hist_kernel(const int* __restrict__ ei) {
    int e = blockIdx.x * blockDim.x + threadIdx.x;
    if (e >= N_EDGES) return;
    atomicAdd(&g_hist[ei[N_EDGES + e]], 1);
}

/* --------------- parallel scan: stage A (per-block scan of 1024) -------- */
__global__ void scanA_kernel() {
    __shared__ int wsum[8];
    int tid = threadIdx.x;                /* 256 */
    int lane = tid & 31, wid = tid >> 5;
    int idx = blockIdx.x * 1024 + tid * 4;

    int v0 = (idx + 0 < N_ATOMS) ? g_hist[idx + 0] : 0;
    int v1 = (idx + 1 < N_ATOMS) ? g_hist[idx + 1] : 0;
    int v2 = (idx + 2 < N_ATOMS) ? g_hist[idx + 2] : 0;
    int v3 = (idx + 3 < N_ATOMS) ? g_hist[idx + 3] : 0;
    int s = v0 + v1 + v2 + v3;
    int si = s;
#pragma unroll
    for (int o = 1; o < 32; o <<= 1) {
        int u = __shfl_up_sync(0xffffffffu, si, o);
        if (lane >= o) si += u;
    }
    if (lane == 31) wsum[wid] = si;
    __syncthreads();
    if (wid == 0 && lane < 8) {
        int w = wsum[lane];
#pragma unroll
        for (int o = 1; o < 8; o <<= 1) {
            int u = __shfl_up_sync(0x000000ffu, w, o);
            if (lane >= o) w += u;
        }
        wsum[lane] = w;
    }
    __syncthreads();
    int off = ((wid > 0) ? wsum[wid - 1] : 0) + (si - s);
    if (idx + 0 < N_ATOMS) g_row[idx + 0] = off;
    if (idx + 1 < N_ATOMS) g_row[idx + 1] = off + v0;
    if (idx + 2 < N_ATOMS) g_row[idx + 2] = off + v0 + v1;
    if (idx + 3 < N_ATOMS) g_row[idx + 3] = off + v0 + v1 + v2;
    if (tid == 0) g_part[blockIdx.x] = wsum[7];
}

/* --------------- stage B: scan 98 block partials (1 warp) --------------- */
__global__ void scanB_kernel() {
    int lane = threadIdx.x;               /* 32 */
    int i = lane * 4;
    int v0 = (i + 0 < SCAN_BLK) ? g_part[i + 0] : 0;
    int v1 = (i + 1 < SCAN_BLK) ? g_part[i + 1] : 0;
    int v2 = (i + 2 < SCAN_BLK) ? g_part[i + 2] : 0;
    int v3 = (i + 3 < SCAN_BLK) ? g_part[i + 3] : 0;
    int s = v0 + v1 + v2 + v3;
    int si = s;
#pragma unroll
    for (int o = 1; o < 32; o <<= 1) {
        int u = __shfl_up_sync(0xffffffffu, si, o);
        if (lane >= o) si += u;
    }
    int excl = si - s;
    if (i + 0 < SCAN_BLK) g_part[i + 0] = excl;
    if (i + 1 < SCAN_BLK) g_part[i + 1] = excl + v0;
    if (i + 2 < SCAN_BLK) g_part[i + 2] = excl + v0 + v1;
    if (i + 3 < SCAN_BLK) g_part[i + 3] = excl + v0 + v1 + v2;
    if (lane == 31) g_row[N_ATOMS] = si;
}

/* --------------- stage C: add block offsets, init cursors --------------- */
__global__ void scanC_kernel() {
    int i = blockIdx.x * blockDim.x + threadIdx.x;
    if (i >= N_ATOMS) return;
    int v = g_row[i] + g_part[i >> 10];
    g_row[i] = v;
    g_cur[i] = v;
}

/* --------------- fused distance + scatter into dst-sorted order --------- */
__global__ void scatter_kernel(const int* __restrict__ ei, const float* __restrict__ pos) {
    int e = blockIdx.x * blockDim.x + threadIdx.x;
    if (e >= N_EDGES) return;
    int s = ei[e];
    int t = ei[N_EDGES + e];
    float dx = pos[s * 3 + 0] - pos[t * 3 + 0];
    float dy = pos[s * 3 + 1] - pos[t * 3 + 1];
    float dz = pos[s * 3 + 2] - pos[t * 3 + 2];
    float d = sqrtf(dx * dx + dy * dy + dz * dz);
    int p = atomicAdd(&g_cur[t], 1);
    unsigned int db = __float_as_uint(d);
    g_edata[p] = ((unsigned long long)db << 32) | (unsigned int)s;
}

/* --------------- h = emb[z] --------------------------------------------- */
__global__ void hinit_kernel(const int* __restrict__ z, const float* __restrict__ emb) {
    int i = blockIdx.x * blockDim.x + threadIdx.x;
    if (i >= N_ATOMS * HID) return;
    int n = i >> 6, j = i & 63;
    g_h[i] = emb[z[n] * HID + j];
}

/* --------------- shared 64x64 GEMM micro-tile ---------------------------- */
__device__ __forceinline__ void gemm_tile(const float (*As)[HID], const float (*Ws)[HID],
                                          int tx, int ty, float acc[4][8]) {
#pragma unroll 2
    for (int k4 = 0; k4 < HID; k4 += 4) {
        float4 a[4];
#pragma unroll
        for (int r = 0; r < 4; r++) a[r] = *(const float4*)&As[4 * ty + r][k4];
#pragma unroll
        for (int kk = 0; kk < 4; kk++) {
            float4 w0 = *(const float4*)&Ws[k4 + kk][8 * tx];
            float4 w1 = *(const float4*)&Ws[k4 + kk][8 * tx + 4];
#pragma unroll
            for (int r = 0; r < 4; r++) {
                float av = ((const float*)&a[r])[kk];
                acc[r][0] = fmaf(av, w0.x, acc[r][0]);
                acc[r][1] = fmaf(av, w0.y, acc[r][1]);
                acc[r][2] = fmaf(av, w0.z, acc[r][2]);
                acc[r][3] = fmaf(av, w0.w, acc[r][3]);
                acc[r][4] = fmaf(av, w1.x, acc[r][4]);
                acc[r][5] = fmaf(av, w1.y, acc[r][5]);
                acc[r][6] = fmaf(av, w1.z, acc[r][6]);
                acc[r][7] = fmaf(av, w1.w, acc[r][7]);
            }
        }
    }
}

/* --------------- x = h @ cf_lin1_w (fp16 output) ------------------------- */
__global__ void __launch_bounds__(256) dense_x_kernel(const float* __restrict__ W) {
    __shared__ float As[BM][HID];
    __shared__ float Ws[HID][HID];
    int tid = threadIdx.x;
    int r0 = blockIdx.x * BM;

    for (int i = tid; i < HID * HID / 4; i += 256)
        ((float4*)Ws)[i] = ((const float4*)W)[i];
#pragma unroll
    for (int i = 0; i < 8; i++) {
        int flat = i * 1024 + tid * 4;
        int row = flat >> 6, k = flat & 63;
        int gr = r0 + row;
        float4 v = make_float4(0.f, 0.f, 0.f, 0.f);
        if (gr < N_ATOMS) v = *(const float4*)(g_h + (size_t)gr * HID + k);
        *(float4*)&As[row][k] = v;
    }
    __syncthreads();

    int tx = tid & 7, ty = tid >> 3;
    float acc[4][8];
#pragma unroll
    for (int r = 0; r < 4; r++)
#pragma unroll
        for (int c = 0; c < 8; c++) acc[r][c] = 0.0f;

    gemm_tile(As, Ws, tx, ty, acc);

#pragma unroll
    for (int r = 0; r < 4; r++) {
        int gr = r0 + 4 * ty + r;
        if (gr < N_ATOMS) {
            __half2 tmp[4];
            tmp[0] = __floats2half2_rn(acc[r][0], acc[r][1]);
            tmp[1] = __floats2half2_rn(acc[r][2], acc[r][3]);
            tmp[2] = __floats2half2_rn(acc[r][4], acc[r][5]);
            tmp[3] = __floats2half2_rn(acc[r][6], acc[r][7]);
            *(uint4*)(g_x + (size_t)gr * HID + 8 * tx) = *(uint4*)tmp;
        }
    }
}

/* --------------- message + segment-sum (one warp per dst node) ----------- */
__global__ void aggregate_kernel(int layer) {
    int warp = (blockIdx.x * blockDim.x + threadIdx.x) >> 5;
    int lane = threadIdx.x & 31;
    if (warp >= N_ATOMS) return;

    const __half* tab = g_table + (size_t)layer * TBL_T * HID;
    int beg = g_row[warp];
    int end = g_row[warp + 1];
    int ch = lane * 2;

    float accx = 0.0f, accy = 0.0f;
    for (int base = beg; base < end; base += 32) {
        int cnt = min(32, end - base);
        unsigned long long pk = (lane < cnt) ? __ldcs(&g_edata[base + lane]) : 0ull;
        for (int j = 0; j < cnt; j++) {
            unsigned long long p = __shfl_sync(0xffffffffu, pk, j);
            int s = (int)(unsigned int)(p & 0xffffffffull);
            float d = __uint_as_float((unsigned int)(p >> 32));
            float ft = d * TBL_SCALE;
            int t = (int)ft;
            t = min(t, TBL_T - 2);
            float f = ft - (float)t;
            const __half* row = tab + (size_t)t * HID + ch;
            float2 w0 = __half22float2(*(const __half2*)row);
            float2 w1 = __half22float2(*(const __half2*)(row + HID));
            float2 xv = __half22float2(__ldcs((const __half2*)(g_x + (size_t)s * HID + ch)));
            float wa = fmaf(f, w1.x - w0.x, w0.x);
            float wb = fmaf(f, w1.y - w0.y, w0.y);
            accx = fmaf(xv.x, wa, accx);
            accy = fmaf(xv.y, wb, accy);
        }
    }
    *(float2*)(g_agg + (size_t)warp * HID + ch) = make_float2(accx, accy);
}

/* --------- h += ( ssp(agg@W1 + b1) @ W2 + b2 )  (fused post block) ------- */
__global__ void __launch_bounds__(256) dense_post_kernel(const float* __restrict__ W1,
                                                         const float* __restrict__ b1,
                                                         const float* __restrict__ W2,
                                                         const float* __restrict__ b2) {
    __shared__ float As[BM][HID];
    __shared__ float Ws[HID][HID];
    int tid = threadIdx.x;
    int r0 = blockIdx.x * BM;

    for (int i = tid; i < HID * HID / 4; i += 256)
        ((float4*)Ws)[i] = ((const float4*)W1)[i];
#pragma unroll
    for (int i = 0; i < 8; i++) {
        int flat = i * 1024 + tid * 4;
        int row = flat >> 6, k = flat & 63;
        int gr = r0 + row;
        float4 v = make_float4(0.f, 0.f, 0.f, 0.f);
        if (gr < N_ATOMS) v = *(const float4*)(g_agg + (size_t)gr * HID + k);
        *(float4*)&As[row][k] = v;
    }
    __syncthreads();

    int tx = tid & 7, ty = tid >> 3;
    float acc[4][8];
#pragma unroll
    for (int r = 0; r < 4; r++)
#pragma unroll
        for (int c = 0; c < 8; c++) acc[r][c] = 0.0f;

    gemm_tile(As, Ws, tx, ty, acc);
    __syncthreads();

    float4 bb0 = *(const float4*)&b1[8 * tx];
    float4 bb1 = *(const float4*)&b1[8 * tx + 4];
#pragma unroll
    for (int r = 0; r < 4; r++) {
        float t0 = ssp(acc[r][0] + bb0.x);
        float t1 = ssp(acc[r][1] + bb0.y);
        float t2 = ssp(acc[r][2] + bb0.z);
        float t3 = ssp(acc[r][3] + bb0.w);
        float t4 = ssp(acc[r][4] + bb1.x);
        float t5 = ssp(acc[r][5] + bb1.y);
        float t6 = ssp(acc[r][6] + bb1.z);
        float t7 = ssp(acc[r][7] + bb1.w);
        *(float4*)&As[4 * ty + r][8 * tx]     = make_float4(t0, t1, t2, t3);
        *(float4*)&As[4 * ty + r][8 * tx + 4] = make_float4(t4, t5, t6, t7);
    }
    for (int i = tid; i < HID * HID / 4; i += 256)
        ((float4*)Ws)[i] = ((const float4*)W2)[i];
    __syncthreads();

#pragma unroll
    for (int r = 0; r < 4; r++)
#pragma unroll
        for (int c = 0; c < 8; c++) acc[r][c] = 0.0f;

    gemm_tile(As, Ws, tx, ty, acc);

    float4 cb0 = *(const float4*)&b2[8 * tx];
    float4 cb1 = *(const float4*)&b2[8 * tx + 4];
#pragma unroll
    for (int r = 0; r < 4; r++) {
        int gr = r0 + 4 * ty + r;
        if (gr < N_ATOMS) {
            float* hp = g_h + (size_t)gr * HID + 8 * tx;
            float4 h0 = *(float4*)hp;
            float4 h1 = *(float4*)(hp + 4);
            h0.x += acc[r][0] + cb0.x;  h0.y += acc[r][1] + cb0.y;
            h0.z += acc[r][2] + cb0.z;  h0.w += acc[r][3] + cb0.w;
            h1.x += acc[r][4] + cb1.x;  h1.y += acc[r][5] + cb1.y;
            h1.z += acc[r][6] + cb1.z;  h1.w += acc[r][7] + cb1.w;
            *(float4*)hp       = h0;
            *(float4*)(hp + 4) = h1;
        }
    }
}

/* --------------- readout: per-atom MLP (64->32->1) + molecule sum -------- */
__global__ void readout_kernel(const int* __restrict__ batch,
                               const float* __restrict__ w1, const float* __restrict__ b1,
                               const float* __restrict__ w2, const float* __restrict__ b2) {
    int warp = (blockIdx.x * blockDim.x + threadIdx.x) >> 5;
    int lane = threadIdx.x & 31;
    if (warp >= N_ATOMS) return;

    float h0 = g_h[(size_t)warp * HID + lane];
    float h1 = g_h[(size_t)warp * HID + 32 + lane];

    float acc = b1[lane];
#pragma unroll
    for (int k = 0; k < 32; k++) {
        float hk = __shfl_sync(0xffffffffu, h0, k);
        acc = fmaf(hk, w1[k * 32 + lane], acc);
    }
#pragma unroll
    for (int k = 0; k < 32; k++) {
        float hk = __shfl_sync(0xffffffffu, h1, k);
        acc = fmaf(hk, w1[(32 + k) * 32 + lane], acc);
    }
    float t = ssp(acc) * w2[lane];
#pragma unroll
    for (int o = 16; o > 0; o >>= 1) t += __shfl_xor_sync(0xffffffffu, t, o);
    if (lane == 0) atomicAdd(&g_molsum[batch[warp]], t + b2[0]);
}

/* --------------- out[g] = molsum[g]*fin_w + fin_b ------------------------ */
__global__ void final_kernel(const float* __restrict__ fw, const float* __restrict__ fb,
                             float* __restrict__ out) {
    int g = blockIdx.x * blockDim.x + threadIdx.x;
    if (g < N_MOL) out[g] = g_molsum[g] * fw[0] + fb[0];
}

/* ========================================================================= */
extern "C" void kernel_launch(void* const* d_in, const int* in_sizes, int n_in,
                              void* d_out, int out_size) {
    const int*   z      = (const int*)d_in[0];
    const float* pos    = (const float*)d_in[1];
    const int*   batch  = (const int*)d_in[2];
    const int*   ei     = (const int*)d_in[3];
    const float* emb    = (const float*)d_in[4];
    const float* out_w1 = (const float*)d_in[5];
    const float* out_b1 = (const float*)d_in[6];
    const float* out_w2 = (const float*)d_in[7];
    const float* out_b2 = (const float*)d_in[8];
    const float* fin_w  = (const float*)d_in[9];
    const float* fin_b  = (const float*)d_in[10];
    const float* mlp_w1 = (const float*)d_in[11];
    const float* mlp_b1 = (const float*)d_in[12];
    const float* mlp_w2 = (const float*)d_in[13];
    const float* mlp_b2 = (const float*)d_in[14];
    const float* cf1    = (const float*)d_in[15];
    const float* cf2    = (const float*)d_in[16];
    const float* cf2b   = (const float*)d_in[17];
    const float* intw   = (const float*)d_in[18];
    const float* intb   = (const float*)d_in[19];

    (void)in_sizes; (void)n_in; (void)out_size;

    zero_kernel<<<(N_ATOMS + 255) / 256, 256>>>();
    table_kernel<<<NLAYERS * TBL_T, 64>>>(mlp_w1, mlp_b1, mlp_w2, mlp_b2);
    hist_kernel<<<(N_EDGES + 255) / 256, 256>>>(ei);
    scanA_kernel<<<SCAN_BLK, 256>>>();
    scanB_kernel<<<1, 32>>>();
    scanC_kernel<<<(N_ATOMS + 255) / 256, 256>>>();
    scatter_kernel<<<(N_EDGES + 255) / 256, 256>>>(ei, pos);
    hinit_kernel<<<(N_ATOMS * HID + 255) / 256, 256>>>(z, emb);

    int gemm_blocks = (N_ATOMS + BM - 1) / BM;
    int warp_blocks = (N_ATOMS * 32 + 255) / 256;

    for (int l = 0; l < NLAYERS; l++) {
        dense_x_kernel<<<gemm_blocks, 256>>>(cf1 + (size_t)l * HID * HID);
        aggregate_kernel<<<warp_blocks, 256>>>(l);
        dense_post_kernel<<<gemm_blocks, 256>>>(cf2 + (size_t)l * HID * HID,
                                                cf2b + (size_t)l * HID,
                                                intw + (size_t)l * HID * HID,
                                                intb + (size_t)l * HID);
    }

    readout_kernel<<<warp_blocks, 256>>>(batch, out_w1, out_b1, out_w2, out_b2);
    final_kernel<<<(N_MOL + 255) / 256, 256>>>(fin_w, fin_b, (float*)d_out);
}

// round 3
// speedup vs baseline: 1.3332x; 1.0993x over previous
#include <cuda_runtime.h>
#include <cuda_fp16.h>
#include <math.h>

#define N_ATOMS 100000
#define N_EDGES 3200000
#define N_MOL   2000
#define HID     64
#define NGAUSS  50
#define NLAYERS 3
#define TBL_T   1024
#define TBL_BYTES (TBL_T * HID * 2)        /* 128 KB fp16 */
#define DMAX    8.6603f                    /* >= 5*sqrt(3) */
#define TBL_SCALE ((float)(TBL_T-1) / DMAX)
#define LOG2F_  0.69314718055994530942f
#define PI_OVER_CUTOFF 0.31415926535897932385f
#define BM 128
#define SCAN_BLK 98
#define AGG_BLOCKS 304

/* ------------------------- scratch (no allocs allowed) ------------------ */
__device__ int                g_hist[N_ATOMS];
__device__ int                g_row[N_ATOMS + 1];
__device__ int                g_cur[N_ATOMS];
__device__ int                g_part[128];
__device__ unsigned long long g_edata[N_EDGES];
__device__ __align__(16) __half g_table[NLAYERS * TBL_T * HID];
__device__ float              g_h[(size_t)N_ATOMS * HID];
__device__ __align__(16) __half g_x[(size_t)N_ATOMS * HID];
__device__ float              g_agg[(size_t)N_ATOMS * HID];
__device__ float              g_molsum[N_MOL];

__device__ __forceinline__ float ssp(float v) {
    return fmaxf(v, 0.0f) + log1pf(expf(-fabsf(v))) - LOG2F_;
}

/* ------------------------- zero hist + molsum --------------------------- */
__global__ void zero_kernel() {
    int i = blockIdx.x * blockDim.x + threadIdx.x;
    if (i < N_ATOMS) g_hist[i] = 0;
    if (i < N_MOL)   g_molsum[i] = 0.0f;
}

/* --------------- build W_l(d) lookup table (fp16): [L][T][64] ----------- */
__global__ void table_kernel(const float* __restrict__ w1, const float* __restrict__ b1,
                             const float* __restrict__ w2, const float* __restrict__ b2) {
    int l = blockIdx.x / TBL_T;
    int t = blockIdx.x % TBL_T;
    int j = threadIdx.x;                       /* 64 threads */
    float d = (float)t * (DMAX / (float)(TBL_T - 1));

    __shared__ float rbf[NGAUSS];
    __shared__ float tmp[HID];

    if (j < NGAUSS) {
        float off = (float)j * (10.0f / 49.0f);
        float u = d - off;
        const float coeff = -0.5f * (49.0f / 10.0f) * (49.0f / 10.0f);
        rbf[j] = expf(coeff * u * u);
    }
    __syncthreads();

    float acc = b1[l * HID + j];
    const float* W1 = w1 + (size_t)l * NGAUSS * HID;
#pragma unroll
    for (int k = 0; k < NGAUSS; k++) acc = fmaf(rbf[k], W1[k * HID + j], acc);
    tmp[j] = ssp(acc);
    __syncthreads();

    float acc2 = b2[l * HID + j];
    const float* W2 = w2 + (size_t)l * HID * HID;
#pragma unroll
    for (int k = 0; k < HID; k++) acc2 = fmaf(tmp[k], W2[k * HID + j], acc2);

    float C = 0.5f * (cosf(d * PI_OVER_CUTOFF) + 1.0f);
    g_table[((size_t)l * TBL_T + t) * HID + j] = __float2half_rn(acc2 * C);
}

/* --------------- dst histogram ------------------------------------------ */
__global__ void hist_kernel(const int* __restrict__ ei) {
    int e = blockIdx.x * blockDim.x + threadIdx.x;
    if (e >= N_EDGES) return;
    atomicAdd(&g_hist[ei[N_EDGES + e]], 1);
}

/* --------------- parallel scan stages ----------------------------------- */
__global__ void scanA_kernel() {
    __shared__ int wsum[8];
    int tid = threadIdx.x;                /* 256 */
    int lane = tid & 31, wid = tid >> 5;
    int idx = blockIdx.x * 1024 + tid * 4;

    int v0 = (idx + 0 < N_ATOMS) ? g_hist[idx + 0] : 0;
    int v1 = (idx + 1 < N_ATOMS) ? g_hist[idx + 1] : 0;
    int v2 = (idx + 2 < N_ATOMS) ? g_hist[idx + 2] : 0;
    int v3 = (idx + 3 < N_ATOMS) ? g_hist[idx + 3] : 0;
    int s = v0 + v1 + v2 + v3;
    int si = s;
#pragma unroll
    for (int o = 1; o < 32; o <<= 1) {
        int u = __shfl_up_sync(0xffffffffu, si, o);
        if (lane >= o) si += u;
    }
    if (lane == 31) wsum[wid] = si;
    __syncthreads();
    if (wid == 0 && lane < 8) {
        int w = wsum[lane];
#pragma unroll
        for (int o = 1; o < 8; o <<= 1) {
            int u = __shfl_up_sync(0x000000ffu, w, o);
            if (lane >= o) w += u;
        }
        wsum[lane] = w;
    }
    __syncthreads();
    int off = ((wid > 0) ? wsum[wid - 1] : 0) + (si - s);
    if (idx + 0 < N_ATOMS) g_row[idx + 0] = off;
    if (idx + 1 < N_ATOMS) g_row[idx + 1] = off + v0;
    if (idx + 2 < N_ATOMS) g_row[idx + 2] = off + v0 + v1;
    if (idx + 3 < N_ATOMS) g_row[idx + 3] = off + v0 + v1 + v2;
    if (tid == 0) g_part[blockIdx.x] = wsum[7];
}

__global__ void scanB_kernel() {
    int lane = threadIdx.x;               /* 32 */
    int i = lane * 4;
    int v0 = (i + 0 < SCAN_BLK) ? g_part[i + 0] : 0;
    int v1 = (i + 1 < SCAN_BLK) ? g_part[i + 1] : 0;
    int v2 = (i + 2 < SCAN_BLK) ? g_part[i + 2] : 0;
    int v3 = (i + 3 < SCAN_BLK) ? g_part[i + 3] : 0;
    int s = v0 + v1 + v2 + v3;
    int si = s;
#pragma unroll
    for (int o = 1; o < 32; o <<= 1) {
        int u = __shfl_up_sync(0xffffffffu, si, o);
        if (lane >= o) si += u;
    }
    int excl = si - s;
    if (i + 0 < SCAN_BLK) g_part[i + 0] = excl;
    if (i + 1 < SCAN_BLK) g_part[i + 1] = excl + v0;
    if (i + 2 < SCAN_BLK) g_part[i + 2] = excl + v0 + v1;
    if (i + 3 < SCAN_BLK) g_part[i + 3] = excl + v0 + v1 + v2;
    if (lane == 31) g_row[N_ATOMS] = si;
}

__global__ void scanC_kernel() {
    int i = blockIdx.x * blockDim.x + threadIdx.x;
    if (i >= N_ATOMS) return;
    int v = g_row[i] + g_part[i >> 10];
    g_row[i] = v;
    g_cur[i] = v;
}

/* --------------- fused distance + scatter into dst-sorted order --------- */
__global__ void scatter_kernel(const int* __restrict__ ei, const float* __restrict__ pos) {
    int e = blockIdx.x * blockDim.x + threadIdx.x;
    if (e >= N_EDGES) return;
    int s = ei[e];
    int t = ei[N_EDGES + e];
    float dx = pos[s * 3 + 0] - pos[t * 3 + 0];
    float dy = pos[s * 3 + 1] - pos[t * 3 + 1];
    float dz = pos[s * 3 + 2] - pos[t * 3 + 2];
    float d = sqrtf(dx * dx + dy * dy + dz * dz);
    int p = atomicAdd(&g_cur[t], 1);
    unsigned int db = __float_as_uint(d);
    g_edata[p] = ((unsigned long long)db << 32) | (unsigned int)s;
}

/* --------------- h = emb[z] --------------------------------------------- */
__global__ void hinit_kernel(const int* __restrict__ z, const float* __restrict__ emb) {
    int i = blockIdx.x * blockDim.x + threadIdx.x;
    if (i >= N_ATOMS * HID) return;
    int n = i >> 6, j = i & 63;
    g_h[i] = emb[z[n] * HID + j];
}

/* --------------- shared 64x64 GEMM micro-tile ---------------------------- */
__device__ __forceinline__ void gemm_tile(const float (*As)[HID], const float (*Ws)[HID],
                                          int tx, int ty, float acc[4][8]) {
#pragma unroll 2
    for (int k4 = 0; k4 < HID; k4 += 4) {
        float4 a[4];
#pragma unroll
        for (int r = 0; r < 4; r++) a[r] = *(const float4*)&As[4 * ty + r][k4];
#pragma unroll
        for (int kk = 0; kk < 4; kk++) {
            float4 w0 = *(const float4*)&Ws[k4 + kk][8 * tx];
            float4 w1 = *(const float4*)&Ws[k4 + kk][8 * tx + 4];
#pragma unroll
            for (int r = 0; r < 4; r++) {
                float av = ((const float*)&a[r])[kk];
                acc[r][0] = fmaf(av, w0.x, acc[r][0]);
                acc[r][1] = fmaf(av, w0.y, acc[r][1]);
                acc[r][2] = fmaf(av, w0.z, acc[r][2]);
                acc[r][3] = fmaf(av, w0.w, acc[r][3]);
                acc[r][4] = fmaf(av, w1.x, acc[r][4]);
                acc[r][5] = fmaf(av, w1.y, acc[r][5]);
                acc[r][6] = fmaf(av, w1.z, acc[r][6]);
                acc[r][7] = fmaf(av, w1.w, acc[r][7]);
            }
        }
    }
}

/* --------------- x = h @ cf_lin1_w (fp16 out) — layer 0 only ------------- */
__global__ void __launch_bounds__(256) dense_x_kernel(const float* __restrict__ W) {
    __shared__ float As[BM][HID];
    __shared__ float Ws[HID][HID];
    int tid = threadIdx.x;
    int r0 = blockIdx.x * BM;

    for (int i = tid; i < HID * HID / 4; i += 256)
        ((float4*)Ws)[i] = ((const float4*)W)[i];
#pragma unroll
    for (int i = 0; i < 8; i++) {
        int flat = i * 1024 + tid * 4;
        int row = flat >> 6, k = flat & 63;
        int gr = r0 + row;
        float4 v = make_float4(0.f, 0.f, 0.f, 0.f);
        if (gr < N_ATOMS) v = *(const float4*)(g_h + (size_t)gr * HID + k);
        *(float4*)&As[row][k] = v;
    }
    __syncthreads();

    int tx = tid & 7, ty = tid >> 3;
    float acc[4][8];
#pragma unroll
    for (int r = 0; r < 4; r++)
#pragma unroll
        for (int c = 0; c < 8; c++) acc[r][c] = 0.0f;

    gemm_tile(As, Ws, tx, ty, acc);

#pragma unroll
    for (int r = 0; r < 4; r++) {
        int gr = r0 + 4 * ty + r;
        if (gr < N_ATOMS) {
            __half2 tmp[4];
            tmp[0] = __floats2half2_rn(acc[r][0], acc[r][1]);
            tmp[1] = __floats2half2_rn(acc[r][2], acc[r][3]);
            tmp[2] = __floats2half2_rn(acc[r][4], acc[r][5]);
            tmp[3] = __floats2half2_rn(acc[r][6], acc[r][7]);
            *(uint4*)(g_x + (size_t)gr * HID + 8 * tx) = *(uint4*)tmp;
        }
    }
}

/* --------------- message + segment-sum: smem table, 4-deep pipeline ------ */
__global__ void __launch_bounds__(1024, 1) aggregate_kernel(int layer) {
    extern __shared__ __half s_tab[];

    /* stage table for this layer into smem (128 KB) */
    {
        const uint4* src = (const uint4*)(g_table + (size_t)layer * TBL_T * HID);
        uint4* dst = (uint4*)s_tab;
        for (int i = threadIdx.x; i < TBL_BYTES / 16; i += 1024) dst[i] = src[i];
    }
    __syncthreads();

    int lane = threadIdx.x & 31;
    int wib  = threadIdx.x >> 5;
    int ch   = lane * 2;

    for (int node = blockIdx.x * 32 + wib; node < N_ATOMS; node += gridDim.x * 32) {
        int beg = g_row[node];
        int end = g_row[node + 1];
        float accx = 0.0f, accy = 0.0f;

        for (int base = beg; base < end; base += 32) {
            int cnt = min(32, end - base);
            unsigned long long pk = (lane < cnt) ? __ldcs(&g_edata[base + lane]) : 0ull;

            int j = 0;
            for (; j + 4 <= cnt; j += 4) {
                unsigned long long p0 = __shfl_sync(0xffffffffu, pk, j + 0);
                unsigned long long p1 = __shfl_sync(0xffffffffu, pk, j + 1);
                unsigned long long p2 = __shfl_sync(0xffffffffu, pk, j + 2);
                unsigned long long p3 = __shfl_sync(0xffffffffu, pk, j + 3);

                int s0 = (int)(unsigned int)p0, s1 = (int)(unsigned int)p1;
                int s2 = (int)(unsigned int)p2, s3 = (int)(unsigned int)p3;
                float ft0 = __uint_as_float((unsigned int)(p0 >> 32)) * TBL_SCALE;
                float ft1 = __uint_as_float((unsigned int)(p1 >> 32)) * TBL_SCALE;
                float ft2 = __uint_as_float((unsigned int)(p2 >> 32)) * TBL_SCALE;
                float ft3 = __uint_as_float((unsigned int)(p3 >> 32)) * TBL_SCALE;
                int t0 = min((int)ft0, TBL_T - 2);
                int t1 = min((int)ft1, TBL_T - 2);
                int t2 = min((int)ft2, TBL_T - 2);
                int t3 = min((int)ft3, TBL_T - 2);
                float f0 = ft0 - (float)t0, f1 = ft1 - (float)t1;
                float f2 = ft2 - (float)t2, f3 = ft3 - (float)t3;

                /* issue all 4 gathers first (independent LDGs in flight) */
                __half2 xr0 = *(const __half2*)(g_x + (size_t)s0 * HID + ch);
                __half2 xr1 = *(const __half2*)(g_x + (size_t)s1 * HID + ch);
                __half2 xr2 = *(const __half2*)(g_x + (size_t)s2 * HID + ch);
                __half2 xr3 = *(const __half2*)(g_x + (size_t)s3 * HID + ch);

                __half2 a0 = *(const __half2*)&s_tab[t0 * HID + ch];
                __half2 b0 = *(const __half2*)&s_tab[(t0 + 1) * HID + ch];
                __half2 a1 = *(const __half2*)&s_tab[t1 * HID + ch];
                __half2 b1 = *(const __half2*)&s_tab[(t1 + 1) * HID + ch];
                __half2 a2 = *(const __half2*)&s_tab[t2 * HID + ch];
                __half2 b2 = *(const __half2*)&s_tab[(t2 + 1) * HID + ch];
                __half2 a3 = *(const __half2*)&s_tab[t3 * HID + ch];
                __half2 b3 = *(const __half2*)&s_tab[(t3 + 1) * HID + ch];

                float2 wa0 = __half22float2(a0), wb0 = __half22float2(b0);
                float2 wa1 = __half22float2(a1), wb1 = __half22float2(b1);
                float2 wa2 = __half22float2(a2), wb2 = __half22float2(b2);
                float2 wa3 = __half22float2(a3), wb3 = __half22float2(b3);
                float2 x0 = __half22float2(xr0), x1 = __half22float2(xr1);
                float2 x2 = __half22float2(xr2), x3 = __half22float2(xr3);

                accx = fmaf(x0.x, fmaf(f0, wb0.x - wa0.x, wa0.x), accx);
                accy = fmaf(x0.y, fmaf(f0, wb0.y - wa0.y, wa0.y), accy);
                accx = fmaf(x1.x, fmaf(f1, wb1.x - wa1.x, wa1.x), accx);
                accy = fmaf(x1.y, fmaf(f1, wb1.y - wa1.y, wa1.y), accy);
                accx = fmaf(x2.x, fmaf(f2, wb2.x - wa2.x, wa2.x), accx);
                accy = fmaf(x2.y, fmaf(f2, wb2.y - wa2.y, wa2.y), accy);
                accx = fmaf(x3.x, fmaf(f3, wb3.x - wa3.x, wa3.x), accx);
                accy = fmaf(x3.y, fmaf(f3, wb3.y - wa3.y, wa3.y), accy);
            }
            for (; j < cnt; j++) {
                unsigned long long p = __shfl_sync(0xffffffffu, pk, j);
                int s = (int)(unsigned int)p;
                float ft = __uint_as_float((unsigned int)(p >> 32)) * TBL_SCALE;
                int t = min((int)ft, TBL_T - 2);
                float f = ft - (float)t;
                float2 xv = __half22float2(*(const __half2*)(g_x + (size_t)s * HID + ch));
                float2 w0 = __half22float2(*(const __half2*)&s_tab[t * HID + ch]);
                float2 w1 = __half22float2(*(const __half2*)&s_tab[(t + 1) * HID + ch]);
                accx = fmaf(xv.x, fmaf(f, w1.x - w0.x, w0.x), accx);
                accy = fmaf(xv.y, fmaf(f, w1.y - w0.y, w0.y), accy);
            }
        }
        *(float2*)(g_agg + (size_t)node * HID + ch) = make_float2(accx, accy);
    }
}

/* --------- h += ssp(agg@W1+b1)@W2+b2 ; optionally x = h@W3 (fp16) -------- */
__global__ void __launch_bounds__(256) dense_post_kernel(const float* __restrict__ W1,
                                                         const float* __restrict__ b1,
                                                         const float* __restrict__ W2,
                                                         const float* __restrict__ b2,
                                                         const float* __restrict__ W3,
                                                         int fuse_next) {
    __shared__ float As[BM][HID];
    __shared__ float Ws[HID][HID];
    int tid = threadIdx.x;
    int r0 = blockIdx.x * BM;

    for (int i = tid; i < HID * HID / 4; i += 256)
        ((float4*)Ws)[i] = ((const float4*)W1)[i];
#pragma unroll
    for (int i = 0; i < 8; i++) {
        int flat = i * 1024 + tid * 4;
        int row = flat >> 6, k = flat & 63;
        int gr = r0 + row;
        float4 v = make_float4(0.f, 0.f, 0.f, 0.f);
        if (gr < N_ATOMS) v = *(const float4*)(g_agg + (size_t)gr * HID + k);
        *(float4*)&As[row][k] = v;
    }
    __syncthreads();

    int tx = tid & 7, ty = tid >> 3;
    float acc[4][8];
#pragma unroll
    for (int r = 0; r < 4; r++)
#pragma unroll
        for (int c = 0; c < 8; c++) acc[r][c] = 0.0f;

    gemm_tile(As, Ws, tx, ty, acc);
    __syncthreads();

    float4 bb0 = *(const float4*)&b1[8 * tx];
    float4 bb1 = *(const float4*)&b1[8 * tx + 4];
#pragma unroll
    for (int r = 0; r < 4; r++) {
        float t0 = ssp(acc[r][0] + bb0.x);
        float t1 = ssp(acc[r][1] + bb0.y);
        float t2 = ssp(acc[r][2] + bb0.z);
        float t3 = ssp(acc[r][3] + bb0.w);
        float t4 = ssp(acc[r][4] + bb1.x);
        float t5 = ssp(acc[r][5] + bb1.y);
        float t6 = ssp(acc[r][6] + bb1.z);
        float t7 = ssp(acc[r][7] + bb1.w);
        *(float4*)&As[4 * ty + r][8 * tx]     = make_float4(t0, t1, t2, t3);
        *(float4*)&As[4 * ty + r][8 * tx + 4] = make_float4(t4, t5, t6, t7);
    }
    for (int i = tid; i < HID * HID / 4; i += 256)
        ((float4*)Ws)[i] = ((const float4*)W2)[i];
    __syncthreads();

#pragma unroll
    for (int r = 0; r < 4; r++)
#pragma unroll
        for (int c = 0; c < 8; c++) acc[r][c] = 0.0f;

    gemm_tile(As, Ws, tx, ty, acc);

    /* residual add -> new h (registers), write g_h */
    float hv[4][8];
    float4 cb0 = *(const float4*)&b2[8 * tx];
    float4 cb1 = *(const float4*)&b2[8 * tx + 4];
#pragma unroll
    for (int r = 0; r < 4; r++) {
        int gr = r0 + 4 * ty + r;
        if (gr < N_ATOMS) {
            float* hp = g_h + (size_t)gr * HID + 8 * tx;
            float4 h0 = *(float4*)hp;
            float4 h1 = *(float4*)(hp + 4);
            hv[r][0] = h0.x + acc[r][0] + cb0.x;
            hv[r][1] = h0.y + acc[r][1] + cb0.y;
            hv[r][2] = h0.z + acc[r][2] + cb0.z;
            hv[r][3] = h0.w + acc[r][3] + cb0.w;
            hv[r][4] = h1.x + acc[r][4] + cb1.x;
            hv[r][5] = h1.y + acc[r][5] + cb1.y;
            hv[r][6] = h1.z + acc[r][6] + cb1.z;
            hv[r][7] = h1.w + acc[r][7] + cb1.w;
            *(float4*)hp       = make_float4(hv[r][0], hv[r][1], hv[r][2], hv[r][3]);
            *(float4*)(hp + 4) = make_float4(hv[r][4], hv[r][5], hv[r][6], hv[r][7]);
        } else {
#pragma unroll
            for (int c = 0; c < 8; c++) hv[r][c] = 0.0f;
        }
    }

    if (!fuse_next) return;

    /* third GEMM: x = h_new @ W3, fp16 output */
    __syncthreads();           /* done reading As/Ws from GEMM2 */
#pragma unroll
    for (int r = 0; r < 4; r++) {
        *(float4*)&As[4 * ty + r][8 * tx]     = make_float4(hv[r][0], hv[r][1], hv[r][2], hv[r][3]);
        *(float4*)&As[4 * ty + r][8 * tx + 4] = make_float4(hv[r][4], hv[r][5], hv[r][6], hv[r][7]);
    }
    for (int i = tid; i < HID * HID / 4; i += 256)
        ((float4*)Ws)[i] = ((const float4*)W3)[i];
    __syncthreads();

#pragma unroll
    for (int r = 0; r < 4; r++)
#pragma unroll
        for (int c = 0; c < 8; c++) acc[r][c] = 0.0f;

    gemm_tile(As, Ws, tx, ty, acc);

#pragma unroll
    for (int r = 0; r < 4; r++) {
        int gr = r0 + 4 * ty + r;
        if (gr < N_ATOMS) {
            __half2 tmp[4];
            tmp[0] = __floats2half2_rn(acc[r][0], acc[r][1]);
            tmp[1] = __floats2half2_rn(acc[r][2], acc[r][3]);
            tmp[2] = __floats2half2_rn(acc[r][4], acc[r][5]);
            tmp[3] = __floats2half2_rn(acc[r][6], acc[r][7]);
            *(uint4*)(g_x + (size_t)gr * HID + 8 * tx) = *(uint4*)tmp;
        }
    }
}

/* --------------- readout: per-atom MLP (64->32->1) + molecule sum -------- */
__global__ void readout_kernel(const int* __restrict__ batch,
                               const float* __restrict__ w1, const float* __restrict__ b1,
                               const float* __restrict__ w2, const float* __restrict__ b2) {
    int warp = (blockIdx.x * blockDim.x + threadIdx.x) >> 5;
    int lane = threadIdx.x & 31;
    if (warp >= N_ATOMS) return;

    float h0 = g_h[(size_t)warp * HID + lane];
    float h1 = g_h[(size_t)warp * HID + 32 + lane];

    float acc = b1[lane];
#pragma unroll
    for (int k = 0; k < 32; k++) {
        float hk = __shfl_sync(0xffffffffu, h0, k);
        acc = fmaf(hk, w1[k * 32 + lane], acc);
    }
#pragma unroll
    for (int k = 0; k < 32; k++) {
        float hk = __shfl_sync(0xffffffffu, h1, k);
        acc = fmaf(hk, w1[(32 + k) * 32 + lane], acc);
    }
    float t = ssp(acc) * w2[lane];
#pragma unroll
    for (int o = 16; o > 0; o >>= 1) t += __shfl_xor_sync(0xffffffffu, t, o);
    if (lane == 0) atomicAdd(&g_molsum[batch[warp]], t + b2[0]);
}

/* --------------- out[g] = molsum[g]*fin_w + fin_b ------------------------ */
__global__ void final_kernel(const float* __restrict__ fw, const float* __restrict__ fb,
                             float* __restrict__ out) {
    int g = blockIdx.x * blockDim.x + threadIdx.x;
    if (g < N_MOL) out[g] = g_molsum[g] * fw[0] + fb[0];
}

/* ========================================================================= */
extern "C" void kernel_launch(void* const* d_in, const int* in_sizes, int n_in,
                              void* d_out, int out_size) {
    const int*   z      = (const int*)d_in[0];
    const float* pos    = (const float*)d_in[1];
    const int*   batch  = (const int*)d_in[2];
    const int*   ei     = (const int*)d_in[3];
    const float* emb    = (const float*)d_in[4];
    const float* out_w1 = (const float*)d_in[5];
    const float* out_b1 = (const float*)d_in[6];
    const float* out_w2 = (const float*)d_in[7];
    const float* out_b2 = (const float*)d_in[8];
    const float* fin_w  = (const float*)d_in[9];
    const float* fin_b  = (const float*)d_in[10];
    const float* mlp_w1 = (const float*)d_in[11];
    const float* mlp_b1 = (const float*)d_in[12];
    const float* mlp_w2 = (const float*)d_in[13];
    const float* mlp_b2 = (const float*)d_in[14];
    const float* cf1    = (const float*)d_in[15];
    const float* cf2    = (const float*)d_in[16];
    const float* cf2b   = (const float*)d_in[17];
    const float* intw   = (const float*)d_in[18];
    const float* intb   = (const float*)d_in[19];

    (void)in_sizes; (void)n_in; (void)out_size;

    static int smem_set = 0;
    if (!smem_set) {
        cudaFuncSetAttribute(aggregate_kernel,
                             cudaFuncAttributeMaxDynamicSharedMemorySize, TBL_BYTES);
        smem_set = 1;
    }

    zero_kernel<<<(N_ATOMS + 255) / 256, 256>>>();
    table_kernel<<<NLAYERS * TBL_T, 64>>>(mlp_w1, mlp_b1, mlp_w2, mlp_b2);
    hist_kernel<<<(N_EDGES + 255) / 256, 256>>>(ei);
    scanA_kernel<<<SCAN_BLK, 256>>>();
    scanB_kernel<<<1, 32>>>();
    scanC_kernel<<<(N_ATOMS + 255) / 256, 256>>>();
    scatter_kernel<<<(N_EDGES + 255) / 256, 256>>>(ei, pos);
    hinit_kernel<<<(N_ATOMS * HID + 255) / 256, 256>>>(z, emb);

    int gemm_blocks = (N_ATOMS + BM - 1) / BM;
    int warp_blocks = (N_ATOMS * 32 + 255) / 256;

    dense_x_kernel<<<gemm_blocks, 256>>>(cf1);   /* layer 0 x */
    for (int l = 0; l < NLAYERS; l++) {
        aggregate_kernel<<<AGG_BLOCKS, 1024, TBL_BYTES>>>(l);
        int fuse = (l + 1 < NLAYERS);
        dense_post_kernel<<<gemm_blocks, 256>>>(cf2 + (size_t)l * HID * HID,
                                                cf2b + (size_t)l * HID,
                                                intw + (size_t)l * HID * HID,
                                                intb + (size_t)l * HID,
                                                cf1 + (size_t)(l + 1 < NLAYERS ? l + 1 : 0) * HID * HID,
                                                fuse);
    }

    readout_kernel<<<warp_blocks, 256>>>(batch, out_w1, out_b1, out_w2, out_b2);
    final_kernel<<<(N_MOL + 255) / 256, 256>>>(fin_w, fin_b, (float*)d_out);
}

// round 4
// speedup vs baseline: 1.6571x; 1.2429x over previous
#include <cuda_runtime.h>
#include <cuda_fp16.h>
#include <mma.h>
#include <math.h>

using namespace nvcuda;

#define N_ATOMS 100000
#define N_EDGES 3200000
#define N_MOL   2000
#define HID     64
#define NGAUSS  50
#define NLAYERS 3
#define TBL_T   1024
#define TBL_BYTES (TBL_T * HID * 2)        /* 128 KB fp16 */
#define DMAX    8.6603f                    /* >= 5*sqrt(3) */
#define TBL_SCALE ((float)(TBL_T-1) / DMAX)
#define LOG2F_  0.69314718055994530942f
#define PI_OVER_CUTOFF 0.31415926535897932385f
#define SCAN_BLK 98
#define AGG_BLOCKS 304
#define TB_TPB  16

/* dense smem layout (halves padded to 72, floats to 68) */
#define LDA 72
#define LDC 68
#define SM_A_OFF  0
#define SM_B_OFF  (128 * LDA * 2)
#define SM_C_OFF  (SM_B_OFF + 64 * LDA * 2)
#define SM_TOTAL  (SM_C_OFF + 128 * LDC * 4)   /* 62464 B */

/* ------------------------- scratch (no allocs allowed) ------------------ */
__device__ int                g_hist[N_ATOMS];
__device__ int                g_row[N_ATOMS + 1];
__device__ int                g_cur[N_ATOMS];
__device__ int                g_part[128];
__device__ unsigned long long g_edata[N_EDGES];
__device__ __align__(16) __half g_table[NLAYERS * TBL_T * HID];
__device__ float              g_h[(size_t)N_ATOMS * HID];
__device__ __align__(16) __half g_x[(size_t)N_ATOMS * HID];
__device__ __align__(16) __half g_aggh[(size_t)N_ATOMS * HID];
__device__ float              g_molsum[N_MOL];
__device__ __align__(16) __half g_cf1h[NLAYERS * HID * HID];
__device__ __align__(16) __half g_cf2h[NLAYERS * HID * HID];
__device__ __align__(16) __half g_inth[NLAYERS * HID * HID];

__device__ __forceinline__ float ssp(float v) {
    return fmaxf(v, 0.0f) + log1pf(expf(-fabsf(v))) - LOG2F_;
}

/* ------------------------- zero hist + molsum --------------------------- */
__global__ void zero_kernel() {
    int i = blockIdx.x * blockDim.x + threadIdx.x;
    if (i < N_ATOMS) g_hist[i] = 0;
    if (i < N_MOL)   g_molsum[i] = 0.0f;
}

/* --------------- weights -> fp16 ---------------------------------------- */
__global__ void wprep_kernel(const float* __restrict__ cf1,
                             const float* __restrict__ cf2,
                             const float* __restrict__ intw) {
    int i = blockIdx.x * 256 + threadIdx.x;
    if (i < NLAYERS * HID * HID) {
        g_cf1h[i] = __float2half_rn(cf1[i]);
        g_cf2h[i] = __float2half_rn(cf2[i]);
        g_inth[i] = __float2half_rn(intw[i]);
    }
}

/* --------------- build W_l(d) lookup table (fp16), weights in smem ------ */
__global__ void __launch_bounds__(256) table_kernel(
        const float* __restrict__ w1, const float* __restrict__ b1,
        const float* __restrict__ w2, const float* __restrict__ b2) {
    __shared__ float W1s[NGAUSS][HID];
    __shared__ float W2s[HID][HID];
    __shared__ float rbfs[TB_TPB][NGAUSS];
    __shared__ float tmps[TB_TPB][HID];

    int l = blockIdx.x / (TBL_T / TB_TPB);
    int tbase = (blockIdx.x % (TBL_T / TB_TPB)) * TB_TPB;
    int tid = threadIdx.x;

    for (int i = tid; i < NGAUSS * HID; i += 256)
        W1s[i / HID][i % HID] = w1[(size_t)l * NGAUSS * HID + i];
    for (int i = tid; i < HID * HID; i += 256)
        W2s[i >> 6][i & 63] = w2[(size_t)l * HID * HID + i];
    for (int i = tid; i < TB_TPB * NGAUSS; i += 256) {
        int tt = i / NGAUSS, k = i % NGAUSS;
        float d = (float)(tbase + tt) * (DMAX / (float)(TBL_T - 1));
        float off = (float)k * (10.0f / 49.0f);
        float u = d - off;
        const float coeff = -0.5f * (49.0f / 10.0f) * (49.0f / 10.0f);
        rbfs[tt][k] = expf(coeff * u * u);
    }
    __syncthreads();

    for (int i = tid; i < TB_TPB * HID; i += 256) {
        int tt = i >> 6, j = i & 63;
        float acc = b1[l * HID + j];
#pragma unroll
        for (int k = 0; k < NGAUSS; k++) acc = fmaf(rbfs[tt][k], W1s[k][j], acc);
        tmps[tt][j] = ssp(acc);
    }
    __syncthreads();

    for (int i = tid; i < TB_TPB * HID; i += 256) {
        int tt = i >> 6, j = i & 63;
        float acc = b2[l * HID + j];
#pragma unroll
        for (int k = 0; k < HID; k++) acc = fmaf(tmps[tt][k], W2s[k][j], acc);
        float d = (float)(tbase + tt) * (DMAX / (float)(TBL_T - 1));
        float C = 0.5f * (cosf(d * PI_OVER_CUTOFF) + 1.0f);
        g_table[((size_t)l * TBL_T + tbase + tt) * HID + j] = __float2half_rn(acc * C);
    }
}

/* --------------- dst histogram ------------------------------------------ */
__global__ void hist_kernel(const int* __restrict__ ei) {
    int e = blockIdx.x * blockDim.x + threadIdx.x;
    if (e >= N_EDGES) return;
    atomicAdd(&g_hist[ei[N_EDGES + e]], 1);
}

/* --------------- parallel scan stages ----------------------------------- */
__global__ void scanA_kernel() {
    __shared__ int wsum[8];
    int tid = threadIdx.x;
    int lane = tid & 31, wid = tid >> 5;
    int idx = blockIdx.x * 1024 + tid * 4;

    int v0 = (idx + 0 < N_ATOMS) ? g_hist[idx + 0] : 0;
    int v1 = (idx + 1 < N_ATOMS) ? g_hist[idx + 1] : 0;
    int v2 = (idx + 2 < N_ATOMS) ? g_hist[idx + 2] : 0;
    int v3 = (idx + 3 < N_ATOMS) ? g_hist[idx + 3] : 0;
    int s = v0 + v1 + v2 + v3;
    int si = s;
#pragma unroll
    for (int o = 1; o < 32; o <<= 1) {
        int u = __shfl_up_sync(0xffffffffu, si, o);
        if (lane >= o) si += u;
    }
    if (lane == 31) wsum[wid] = si;
    __syncthreads();
    if (wid == 0 && lane < 8) {
        int w = wsum[lane];
#pragma unroll
        for (int o = 1; o < 8; o <<= 1) {
            int u = __shfl_up_sync(0x000000ffu, w, o);
            if (lane >= o) w += u;
        }
        wsum[lane] = w;
    }
    __syncthreads();
    int off = ((wid > 0) ? wsum[wid - 1] : 0) + (si - s);
    if (idx + 0 < N_ATOMS) g_row[idx + 0] = off;
    if (idx + 1 < N_ATOMS) g_row[idx + 1] = off + v0;
    if (idx + 2 < N_ATOMS) g_row[idx + 2] = off + v0 + v1;
    if (idx + 3 < N_ATOMS) g_row[idx + 3] = off + v0 + v1 + v2;
    if (tid == 0) g_part[blockIdx.x] = wsum[7];
}

__global__ void scanB_kernel() {
    int lane = threadIdx.x;
    int i = lane * 4;
    int v0 = (i + 0 < SCAN_BLK) ? g_part[i + 0] : 0;
    int v1 = (i + 1 < SCAN_BLK) ? g_part[i + 1] : 0;
    int v2 = (i + 2 < SCAN_BLK) ? g_part[i + 2] : 0;
    int v3 = (i + 3 < SCAN_BLK) ? g_part[i + 3] : 0;
    int s = v0 + v1 + v2 + v3;
    int si = s;
#pragma unroll
    for (int o = 1; o < 32; o <<= 1) {
        int u = __shfl_up_sync(0xffffffffu, si, o);
        if (lane >= o) si += u;
    }
    int excl = si - s;
    if (i + 0 < SCAN_BLK) g_part[i + 0] = excl;
    if (i + 1 < SCAN_BLK) g_part[i + 1] = excl + v0;
    if (i + 2 < SCAN_BLK) g_part[i + 2] = excl + v0 + v1;
    if (i + 3 < SCAN_BLK) g_part[i + 3] = excl + v0 + v1 + v2;
    if (lane == 31) g_row[N_ATOMS] = si;
}

__global__ void scanC_kernel() {
    int i = blockIdx.x * blockDim.x + threadIdx.x;
    if (i >= N_ATOMS) return;
    int v = g_row[i] + g_part[i >> 10];
    g_row[i] = v;
    g_cur[i] = v;
}

/* ------- fused distance + (t,f) precompute + scatter into dst order ----- */
__global__ void scatter_kernel(const int* __restrict__ ei, const float* __restrict__ pos) {
    int e = blockIdx.x * blockDim.x + threadIdx.x;
    if (e >= N_EDGES) return;
    int s = ei[e];
    int t = ei[N_EDGES + e];
    float dx = pos[s * 3 + 0] - pos[t * 3 + 0];
    float dy = pos[s * 3 + 1] - pos[t * 3 + 1];
    float dz = pos[s * 3 + 2] - pos[t * 3 + 2];
    float d = sqrtf(dx * dx + dy * dy + dz * dz);
    float ft = d * TBL_SCALE;
    int ti = min((int)ft, TBL_T - 2);
    float f = ft - (float)ti;
    unsigned short fh = __half_as_ushort(__float2half_rn(f));
    int p = atomicAdd(&g_cur[t], 1);
    g_edata[p] = ((unsigned long long)(unsigned int)s << 32) |
                 ((unsigned int)ti << 16) | (unsigned int)fh;
}

/* --------------- h = emb[z] --------------------------------------------- */
__global__ void hinit_kernel(const int* __restrict__ z, const float* __restrict__ emb) {
    int i = blockIdx.x * blockDim.x + threadIdx.x;
    if (i >= N_ATOMS * HID) return;
    int n = i >> 6, j = i & 63;
    g_h[i] = emb[z[n] * HID + j];
}

/* --------------- wmma 128x64x64 tile: C(f32 smem) = A(h) @ B(h) ---------- */
__device__ __forceinline__ void wmma_gemm(const __half* sA, const __half* sB, float* sC) {
    int w = threadIdx.x >> 5;      /* 8 warps, warp w -> rows 16w..16w+15 */
    wmma::fragment<wmma::accumulator, 16, 16, 16, float> c[4];
#pragma unroll
    for (int n = 0; n < 4; n++) wmma::fill_fragment(c[n], 0.0f);
#pragma unroll
    for (int k = 0; k < 4; k++) {
        wmma::fragment<wmma::matrix_a, 16, 16, 16, __half, wmma::row_major> a;
        wmma::load_matrix_sync(a, sA + (w * 16) * LDA + k * 16, LDA);
#pragma unroll
        for (int n = 0; n < 4; n++) {
            wmma::fragment<wmma::matrix_b, 16, 16, 16, __half, wmma::row_major> b;
            wmma::load_matrix_sync(b, sB + (k * 16) * LDA + n * 16, LDA);
            wmma::mma_sync(c[n], a, b, c[n]);
        }
    }
#pragma unroll
    for (int n = 0; n < 4; n++)
        wmma::store_matrix_sync(sC + (w * 16) * LDC + n * 16, c[n], LDC, wmma::mem_row_major);
}

__device__ __forceinline__ void load_B(__half* sB, const __half* W, int tid) {
    for (int i = tid; i < 64 * 32; i += 256) {
        int row = i >> 5, c2 = i & 31;
        *(unsigned int*)&sB[row * LDA + c2 * 2] = ((const unsigned int*)W)[row * 32 + c2];
    }
}

/* --------------- x = h @ cf1[0] (tensor core) ---------------------------- */
__global__ void __launch_bounds__(256) dense_x_w() {
    extern __shared__ char sm[];
    __half* sA = (__half*)(sm + SM_A_OFF);
    __half* sB = (__half*)(sm + SM_B_OFF);
    float*  sC = (float*)(sm + SM_C_OFF);
    int tid = threadIdx.x;
    size_t r0 = (size_t)blockIdx.x * 128;

    for (int i = tid; i < 128 * 64; i += 256) {
        int row = i >> 6, col = i & 63;
        float v = (r0 + row < N_ATOMS) ? g_h[(r0 + row) * HID + col] : 0.0f;
        sA[row * LDA + col] = __float2half_rn(v);
    }
    load_B(sB, g_cf1h, tid);
    __syncthreads();
    wmma_gemm(sA, sB, sC);
    __syncthreads();
    for (int i = tid; i < 128 * 32; i += 256) {
        int row = i >> 5, c2 = i & 31;
        size_t gr = r0 + row;
        if (gr < N_ATOMS) {
            __half2 hv = __floats2half2_rn(sC[row * LDC + c2 * 2], sC[row * LDC + c2 * 2 + 1]);
            *(__half2*)(g_x + gr * HID + c2 * 2) = hv;
        }
    }
}

/* --------------- message + segment-sum (smem table, packed edges) -------- */
__device__ __forceinline__ void edge_op(unsigned long long p, const __half* s_tab,
                                        const __half2* xbase, int lane, int ch,
                                        float& accx, float& accy) {
    unsigned int s_ = (unsigned int)(p >> 32);
    unsigned int lo = (unsigned int)p;
    int t_ = (int)(lo >> 16);
    __half2 f2 = __half2half2(__ushort_as_half((unsigned short)(lo & 0xffffu)));
    __half2 xv = xbase[(size_t)s_ * 32u + lane];
    __half2 a = *(const __half2*)(s_tab + (size_t)t_ * HID + ch);
    __half2 b = *(const __half2*)(s_tab + (size_t)t_ * HID + HID + ch);
    __half2 w = __hfma2(f2, __hsub2(b, a), a);
    float2 wf = __half22float2(w);
    float2 xf = __half22float2(xv);
    accx = fmaf(wf.x, xf.x, accx);
    accy = fmaf(wf.y, xf.y, accy);
}

__global__ void __launch_bounds__(1024, 1) aggregate_kernel(int layer) {
    extern __shared__ __half s_tab[];
    {
        const uint4* src = (const uint4*)(g_table + (size_t)layer * TBL_T * HID);
        uint4* dst = (uint4*)s_tab;
        for (int i = threadIdx.x; i < TBL_BYTES / 16; i += 1024) dst[i] = src[i];
    }
    __syncthreads();

    int lane = threadIdx.x & 31;
    int wib  = threadIdx.x >> 5;
    int ch   = lane * 2;
    const __half2* xbase = (const __half2*)g_x;

    for (int node = blockIdx.x * 32 + wib; node < N_ATOMS; node += gridDim.x * 32) {
        int beg = g_row[node];
        int end = g_row[node + 1];
        float accx = 0.0f, accy = 0.0f;

        for (int base = beg; base < end; base += 32) {
            int cnt = min(32, end - base);
            unsigned long long pk = (lane < cnt) ? __ldcs(&g_edata[base + lane]) : 0ull;
            int j = 0;
            for (; j + 4 <= cnt; j += 4) {
                unsigned long long p0 = __shfl_sync(0xffffffffu, pk, j + 0);
                unsigned long long p1 = __shfl_sync(0xffffffffu, pk, j + 1);
                unsigned long long p2 = __shfl_sync(0xffffffffu, pk, j + 2);
                unsigned long long p3 = __shfl_sync(0xffffffffu, pk, j + 3);
                edge_op(p0, s_tab, xbase, lane, ch, accx, accy);
                edge_op(p1, s_tab, xbase, lane, ch, accx, accy);
                edge_op(p2, s_tab, xbase, lane, ch, accx, accy);
                edge_op(p3, s_tab, xbase, lane, ch, accx, accy);
            }
            for (; j < cnt; j++) {
                unsigned long long p = __shfl_sync(0xffffffffu, pk, j);
                edge_op(p, s_tab, xbase, lane, ch, accx, accy);
            }
        }
        *(__half2*)(g_aggh + (size_t)node * HID + ch) = __floats2half2_rn(accx, accy);
    }
}

/* --- h += ssp(agg@W1+b1)@W2+b2 ; x = h_new@W3 (all tensor-core) ---------- */
__global__ void __launch_bounds__(256) dense_post_w(int l, int fuse_next,
                                                    const float* __restrict__ b1,
                                                    const float* __restrict__ b2) {
    extern __shared__ char sm[];
    __half* sA = (__half*)(sm + SM_A_OFF);
    __half* sB = (__half*)(sm + SM_B_OFF);
    float*  sC = (float*)(sm + SM_C_OFF);
    int tid = threadIdx.x;
    size_t r0 = (size_t)blockIdx.x * 128;

    const __half* W1 = g_cf2h + (size_t)l * HID * HID;
    const __half* W2 = g_inth + (size_t)l * HID * HID;
    const __half* W3 = g_cf1h + (size_t)(l + 1 < NLAYERS ? l + 1 : 0) * HID * HID;

    /* A = agg (half) */
    for (int i = tid; i < 128 * 32; i += 256) {
        int row = i >> 5, c2 = i & 31;
        unsigned int v = 0;
        if (r0 + row < N_ATOMS)
            v = ((const unsigned int*)g_aggh)[(r0 + row) * 32 + c2];
        *(unsigned int*)&sA[row * LDA + c2 * 2] = v;
    }
    load_B(sB, W1, tid);
    __syncthreads();
    wmma_gemm(sA, sB, sC);
    __syncthreads();

    /* A = half(ssp(C + b1)) ; B = W2 */
    for (int i = tid; i < 128 * 64; i += 256) {
        int row = i >> 6, col = i & 63;
        float v = ssp(sC[row * LDC + col] + __ldg(&b1[col]));
        sA[row * LDA + col] = __float2half_rn(v);
    }
    load_B(sB, W2, tid);
    __syncthreads();
    wmma_gemm(sA, sB, sC);
    __syncthreads();

    /* h_new = h + C + b2 -> g_h ; A = half(h_new) */
    for (int i = tid; i < 128 * 64; i += 256) {
        int row = i >> 6, col = i & 63;
        size_t gr = r0 + row;
        float v = 0.0f;
        if (gr < N_ATOMS) {
            v = g_h[gr * HID + col] + sC[row * LDC + col] + __ldg(&b2[col]);
            g_h[gr * HID + col] = v;
        }
        sA[row * LDA + col] = __float2half_rn(v);
    }
    if (!fuse_next) return;

    load_B(sB, W3, tid);
    __syncthreads();
    wmma_gemm(sA, sB, sC);
    __syncthreads();
    for (int i = tid; i < 128 * 32; i += 256) {
        int row = i >> 5, c2 = i & 31;
        size_t gr = r0 + row;
        if (gr < N_ATOMS) {
            __half2 hv = __floats2half2_rn(sC[row * LDC + c2 * 2], sC[row * LDC + c2 * 2 + 1]);
            *(__half2*)(g_x + gr * HID + c2 * 2) = hv;
        }
    }
}

/* --------------- readout: per-atom MLP (64->32->1) + molecule sum -------- */
__global__ void readout_kernel(const int* __restrict__ batch,
                               const float* __restrict__ w1, const float* __restrict__ b1,
                               const float* __restrict__ w2, const float* __restrict__ b2) {
    int warp = (blockIdx.x * blockDim.x + threadIdx.x) >> 5;
    int lane = threadIdx.x & 31;
    if (warp >= N_ATOMS) return;

    float h0 = g_h[(size_t)warp * HID + lane];
    float h1 = g_h[(size_t)warp * HID + 32 + lane];

    float acc = b1[lane];
#pragma unroll
    for (int k = 0; k < 32; k++) {
        float hk = __shfl_sync(0xffffffffu, h0, k);
        acc = fmaf(hk, w1[k * 32 + lane], acc);
    }
#pragma unroll
    for (int k = 0; k < 32; k++) {
        float hk = __shfl_sync(0xffffffffu, h1, k);
        acc = fmaf(hk, w1[(32 + k) * 32 + lane], acc);
    }
    float t = ssp(acc) * w2[lane];
#pragma unroll
    for (int o = 16; o > 0; o >>= 1) t += __shfl_xor_sync(0xffffffffu, t, o);
    if (lane == 0) atomicAdd(&g_molsum[batch[warp]], t + b2[0]);
}

/* --------------- out[g] = molsum[g]*fin_w + fin_b ------------------------ */
__global__ void final_kernel(const float* __restrict__ fw, const float* __restrict__ fb,
                             float* __restrict__ out) {
    int g = blockIdx.x * blockDim.x + threadIdx.x;
    if (g < N_MOL) out[g] = g_molsum[g] * fw[0] + fb[0];
}

/* ========================================================================= */
extern "C" void kernel_launch(void* const* d_in, const int* in_sizes, int n_in,
                              void* d_out, int out_size) {
    const int*   z      = (const int*)d_in[0];
    const float* pos    = (const float*)d_in[1];
    const int*   batch  = (const int*)d_in[2];
    const int*   ei     = (const int*)d_in[3];
    const float* emb    = (const float*)d_in[4];
    const float* out_w1 = (const float*)d_in[5];
    const float* out_b1 = (const float*)d_in[6];
    const float* out_w2 = (const float*)d_in[7];
    const float* out_b2 = (const float*)d_in[8];
    const float* fin_w  = (const float*)d_in[9];
    const float* fin_b  = (const float*)d_in[10];
    const float* mlp_w1 = (const float*)d_in[11];
    const float* mlp_b1 = (const float*)d_in[12];
    const float* mlp_w2 = (const float*)d_in[13];
    const float* mlp_b2 = (const float*)d_in[14];
    const float* cf1    = (const float*)d_in[15];
    const float* cf2    = (const float*)d_in[16];
    const float* cf2b   = (const float*)d_in[17];
    const float* intw   = (const float*)d_in[18];
    const float* intb   = (const float*)d_in[19];

    (void)in_sizes; (void)n_in; (void)out_size;

    static int smem_set = 0;
    if (!smem_set) {
        cudaFuncSetAttribute(aggregate_kernel,
                             cudaFuncAttributeMaxDynamicSharedMemorySize, TBL_BYTES);
        cudaFuncSetAttribute(dense_x_w,
                             cudaFuncAttributeMaxDynamicSharedMemorySize, SM_TOTAL);
        cudaFuncSetAttribute(dense_post_w,
                             cudaFuncAttributeMaxDynamicSharedMemorySize, SM_TOTAL);
        smem_set = 1;
    }

    zero_kernel<<<(N_ATOMS + 255) / 256, 256>>>();
    wprep_kernel<<<(NLAYERS * HID * HID + 255) / 256, 256>>>(cf1, cf2, intw);
    table_kernel<<<NLAYERS * (TBL_T / TB_TPB), 256>>>(mlp_w1, mlp_b1, mlp_w2, mlp_b2);
    hist_kernel<<<(N_EDGES + 255) / 256, 256>>>(ei);
    scanA_kernel<<<SCAN_BLK, 256>>>();
    scanB_kernel<<<1, 32>>>();
    scanC_kernel<<<(N_ATOMS + 255) / 256, 256>>>();
    scatter_kernel<<<(N_EDGES + 255) / 256, 256>>>(ei, pos);
    hinit_kernel<<<(N_ATOMS * HID + 255) / 256, 256>>>(z, emb);

    int gemm_blocks = (N_ATOMS + 127) / 128;
    int warp_blocks = (N_ATOMS * 32 + 255) / 256;

    dense_x_w<<<gemm_blocks, 256, SM_TOTAL>>>();
    for (int l = 0; l < NLAYERS; l++) {
        aggregate_kernel<<<AGG_BLOCKS, 1024, TBL_BYTES>>>(l);
        dense_post_w<<<gemm_blocks, 256, SM_TOTAL>>>(l, (l + 1 < NLAYERS),
                                                     cf2b + (size_t)l * HID,
                                                     intb + (size_t)l * HID);
    }

    readout_kernel<<<warp_blocks, 256>>>(batch, out_w1, out_b1, out_w2, out_b2);
    final_kernel<<<(N_MOL + 255) / 256, 256>>>(fin_w, fin_b, (float*)d_out);
}

// round 5
// speedup vs baseline: 1.8124x; 1.0937x over previous
#include <cuda_runtime.h>
#include <cuda_fp16.h>
#include <mma.h>
#include <math.h>

using namespace nvcuda;

#define N_ATOMS 100000
#define N_EDGES 3200000
#define N_MOL   2000
#define HID     64
#define NGAUSS  50
#define NLAYERS 3
#define TBL_T   512
#define TBL2_BYTES (TBL_T * HID * 4)       /* 128 KB: (a,d) interleaved fp16 */
#define DMAX    8.6603f                    /* >= 5*sqrt(3) */
#define TBL_SCALE ((float)(TBL_T-1) / DMAX)
#define LOG2F_  0.69314718055994530942f
#define PI_OVER_CUTOFF 0.31415926535897932385f
#define SCAN_BLK 98
#define AGG_BLOCKS 148
#define TB_TPB  16

/* dense smem layout (halves padded to 72, floats to 68) */
#define LDA 72
#define LDC 68
#define SM_A_OFF  0
#define SM_B_OFF  (128 * LDA * 2)
#define SM_C_OFF  (SM_B_OFF + 64 * LDA * 2)
#define SM_TOTAL  (SM_C_OFF + 128 * LDC * 4)   /* 62464 B */

/* ------------------------- scratch (no allocs allowed) ------------------ */
__device__ int                g_hist[N_ATOMS];
__device__ int                g_row[N_ATOMS + 1];
__device__ int                g_cur[N_ATOMS];
__device__ int                g_part[128];
__device__ unsigned long long g_edata[N_EDGES];
__device__ __align__(16) __half g_traw[NLAYERS * TBL_T * HID];
__device__ __align__(16) __half g_tbl2[NLAYERS * TBL_T * HID * 2];
__device__ float              g_h[(size_t)N_ATOMS * HID];
__device__ __align__(16) __half g_x[(size_t)N_ATOMS * HID];
__device__ __align__(16) __half g_aggh[(size_t)N_ATOMS * HID];
__device__ float              g_molsum[N_MOL];
__device__ __align__(16) __half g_cf1h[NLAYERS * HID * HID];
__device__ __align__(16) __half g_cf2h[NLAYERS * HID * HID];
__device__ __align__(16) __half g_inth[NLAYERS * HID * HID];

__device__ __forceinline__ float ssp(float v) {
    return fmaxf(v, 0.0f) + log1pf(expf(-fabsf(v))) - LOG2F_;
}

/* ------------------------- zero hist + molsum --------------------------- */
__global__ void zero_kernel() {
    int i = blockIdx.x * blockDim.x + threadIdx.x;
    if (i < N_ATOMS) g_hist[i] = 0;
    if (i < N_MOL)   g_molsum[i] = 0.0f;
}

/* --------------- weights -> fp16 ---------------------------------------- */
__global__ void wprep_kernel(const float* __restrict__ cf1,
                             const float* __restrict__ cf2,
                             const float* __restrict__ intw) {
    int i = blockIdx.x * 256 + threadIdx.x;
    if (i < NLAYERS * HID * HID) {
        g_cf1h[i] = __float2half_rn(cf1[i]);
        g_cf2h[i] = __float2half_rn(cf2[i]);
        g_inth[i] = __float2half_rn(intw[i]);
    }
}

/* --------------- build raw W_l(d) table (fp16), weights in smem --------- */
__global__ void __launch_bounds__(256) table_kernel(
        const float* __restrict__ w1, const float* __restrict__ b1,
        const float* __restrict__ w2, const float* __restrict__ b2) {
    __shared__ float W1s[NGAUSS][HID];
    __shared__ float W2s[HID][HID];
    __shared__ float rbfs[TB_TPB][NGAUSS];
    __shared__ float tmps[TB_TPB][HID];

    int l = blockIdx.x / (TBL_T / TB_TPB);
    int tbase = (blockIdx.x % (TBL_T / TB_TPB)) * TB_TPB;
    int tid = threadIdx.x;

    for (int i = tid; i < NGAUSS * HID; i += 256)
        W1s[i / HID][i % HID] = w1[(size_t)l * NGAUSS * HID + i];
    for (int i = tid; i < HID * HID; i += 256)
        W2s[i >> 6][i & 63] = w2[(size_t)l * HID * HID + i];
    for (int i = tid; i < TB_TPB * NGAUSS; i += 256) {
        int tt = i / NGAUSS, k = i % NGAUSS;
        float d = (float)(tbase + tt) * (DMAX / (float)(TBL_T - 1));
        float off = (float)k * (10.0f / 49.0f);
        float u = d - off;
        const float coeff = -0.5f * (49.0f / 10.0f) * (49.0f / 10.0f);
        rbfs[tt][k] = expf(coeff * u * u);
    }
    __syncthreads();

    for (int i = tid; i < TB_TPB * HID; i += 256) {
        int tt = i >> 6, j = i & 63;
        float acc = b1[l * HID + j];
#pragma unroll
        for (int k = 0; k < NGAUSS; k++) acc = fmaf(rbfs[tt][k], W1s[k][j], acc);
        tmps[tt][j] = ssp(acc);
    }
    __syncthreads();

    for (int i = tid; i < TB_TPB * HID; i += 256) {
        int tt = i >> 6, j = i & 63;
        float acc = b2[l * HID + j];
#pragma unroll
        for (int k = 0; k < HID; k++) acc = fmaf(tmps[tt][k], W2s[k][j], acc);
        float d = (float)(tbase + tt) * (DMAX / (float)(TBL_T - 1));
        float C = 0.5f * (cosf(d * PI_OVER_CUTOFF) + 1.0f);
        g_traw[((size_t)l * TBL_T + tbase + tt) * HID + j] = __float2half_rn(acc * C);
    }
}

/* --------------- pack raw -> interleaved (a, delta) ---------------------- */
__global__ void pack_kernel() {
    int i = blockIdx.x * 256 + threadIdx.x;     /* (l, t, c2) */
    if (i >= NLAYERS * TBL_T * 32) return;
    int c2 = i & 31;
    int t  = (i >> 5) & (TBL_T - 1);
    int l  = i >> 14;                           /* 5 + 9 bits */
    const __half2* raw = (const __half2*)g_traw;
    __half2 a = raw[((size_t)l * TBL_T + t) * 32 + c2];
    int tn = (t + 1 < TBL_T) ? t + 1 : t;
    __half2 b = raw[((size_t)l * TBL_T + tn) * 32 + c2];
    __half2 d = __hsub2(b, a);
    __half2* dst = (__half2*)g_tbl2;
    dst[(((size_t)l * TBL_T + t) * 32 + c2) * 2 + 0] = a;
    dst[(((size_t)l * TBL_T + t) * 32 + c2) * 2 + 1] = d;
}

/* --------------- dst histogram ------------------------------------------ */
__global__ void hist_kernel(const int* __restrict__ ei) {
    int e = blockIdx.x * blockDim.x + threadIdx.x;
    if (e >= N_EDGES) return;
    atomicAdd(&g_hist[ei[N_EDGES + e]], 1);
}

/* --------------- parallel scan stages ----------------------------------- */
__global__ void scanA_kernel() {
    __shared__ int wsum[8];
    int tid = threadIdx.x;
    int lane = tid & 31, wid = tid >> 5;
    int idx = blockIdx.x * 1024 + tid * 4;

    int v0 = (idx + 0 < N_ATOMS) ? g_hist[idx + 0] : 0;
    int v1 = (idx + 1 < N_ATOMS) ? g_hist[idx + 1] : 0;
    int v2 = (idx + 2 < N_ATOMS) ? g_hist[idx + 2] : 0;
    int v3 = (idx + 3 < N_ATOMS) ? g_hist[idx + 3] : 0;
    int s = v0 + v1 + v2 + v3;
    int si = s;
#pragma unroll
    for (int o = 1; o < 32; o <<= 1) {
        int u = __shfl_up_sync(0xffffffffu, si, o);
        if (lane >= o) si += u;
    }
    if (lane == 31) wsum[wid] = si;
    __syncthreads();
    if (wid == 0 && lane < 8) {
        int w = wsum[lane];
#pragma unroll
        for (int o = 1; o < 8; o <<= 1) {
            int u = __shfl_up_sync(0x000000ffu, w, o);
            if (lane >= o) w += u;
        }
        wsum[lane] = w;
    }
    __syncthreads();
    int off = ((wid > 0) ? wsum[wid - 1] : 0) + (si - s);
    if (idx + 0 < N_ATOMS) g_row[idx + 0] = off;
    if (idx + 1 < N_ATOMS) g_row[idx + 1] = off + v0;
    if (idx + 2 < N_ATOMS) g_row[idx + 2] = off + v0 + v1;
    if (idx + 3 < N_ATOMS) g_row[idx + 3] = off + v0 + v1 + v2;
    if (tid == 0) g_part[blockIdx.x] = wsum[7];
}

__global__ void scanB_kernel() {
    int lane = threadIdx.x;
    int i = lane * 4;
    int v0 = (i + 0 < SCAN_BLK) ? g_part[i + 0] : 0;
    int v1 = (i + 1 < SCAN_BLK) ? g_part[i + 1] : 0;
    int v2 = (i + 2 < SCAN_BLK) ? g_part[i + 2] : 0;
    int v3 = (i + 3 < SCAN_BLK) ? g_part[i + 3] : 0;
    int s = v0 + v1 + v2 + v3;
    int si = s;
#pragma unroll
    for (int o = 1; o < 32; o <<= 1) {
        int u = __shfl_up_sync(0xffffffffu, si, o);
        if (lane >= o) si += u;
    }
    int excl = si - s;
    if (i + 0 < SCAN_BLK) g_part[i + 0] = excl;
    if (i + 1 < SCAN_BLK) g_part[i + 1] = excl + v0;
    if (i + 2 < SCAN_BLK) g_part[i + 2] = excl + v0 + v1;
    if (i + 3 < SCAN_BLK) g_part[i + 3] = excl + v0 + v1 + v2;
    if (lane == 31) g_row[N_ATOMS] = si;
}

__global__ void scanC_kernel() {
    int i = blockIdx.x * blockDim.x + threadIdx.x;
    if (i >= N_ATOMS) return;
    int v = g_row[i] + g_part[i >> 10];
    g_row[i] = v;
    g_cur[i] = v;
}

/* ------- fused distance + (t,f) precompute + scatter into dst order ----- */
__global__ void scatter_kernel(const int* __restrict__ ei, const float* __restrict__ pos) {
    int e = blockIdx.x * blockDim.x + threadIdx.x;
    if (e >= N_EDGES) return;
    int s = ei[e];
    int t = ei[N_EDGES + e];
    float dx = pos[s * 3 + 0] - pos[t * 3 + 0];
    float dy = pos[s * 3 + 1] - pos[t * 3 + 1];
    float dz = pos[s * 3 + 2] - pos[t * 3 + 2];
    float d = sqrtf(dx * dx + dy * dy + dz * dz);
    float ft = d * TBL_SCALE;
    int ti = min((int)ft, TBL_T - 2);
    float f = ft - (float)ti;
    unsigned short fh = __half_as_ushort(__float2half_rn(f));
    int p = atomicAdd(&g_cur[t], 1);
    g_edata[p] = ((unsigned long long)(unsigned int)s << 32) |
                 ((unsigned int)ti << 16) | (unsigned int)fh;
}

/* --------------- wmma 128x64x64 tile: C(f32 smem) = A(h) @ B(h) ---------- */
__device__ __forceinline__ void wmma_gemm(const __half* sA, const __half* sB, float* sC) {
    int w = threadIdx.x >> 5;
    wmma::fragment<wmma::accumulator, 16, 16, 16, float> c[4];
#pragma unroll
    for (int n = 0; n < 4; n++) wmma::fill_fragment(c[n], 0.0f);
#pragma unroll
    for (int k = 0; k < 4; k++) {
        wmma::fragment<wmma::matrix_a, 16, 16, 16, __half, wmma::row_major> a;
        wmma::load_matrix_sync(a, sA + (w * 16) * LDA + k * 16, LDA);
#pragma unroll
        for (int n = 0; n < 4; n++) {
            wmma::fragment<wmma::matrix_b, 16, 16, 16, __half, wmma::row_major> b;
            wmma::load_matrix_sync(b, sB + (k * 16) * LDA + n * 16, LDA);
            wmma::mma_sync(c[n], a, b, c[n]);
        }
    }
#pragma unroll
    for (int n = 0; n < 4; n++)
        wmma::store_matrix_sync(sC + (w * 16) * LDC + n * 16, c[n], LDC, wmma::mem_row_major);
}

__device__ __forceinline__ void load_B(__half* sB, const __half* W, int tid) {
    for (int i = tid; i < 64 * 32; i += 256) {
        int row = i >> 5, c2 = i & 31;
        *(unsigned int*)&sB[row * LDA + c2 * 2] = ((const unsigned int*)W)[row * 32 + c2];
    }
}

/* ---- x = emb[z] @ cf1[0] (tensor core); also initializes g_h ------------ */
__global__ void __launch_bounds__(256) dense_x_w(const int* __restrict__ z,
                                                 const float* __restrict__ emb) {
    extern __shared__ char sm[];
    __half* sA = (__half*)(sm + SM_A_OFF);
    __half* sB = (__half*)(sm + SM_B_OFF);
    float*  sC = (float*)(sm + SM_C_OFF);
    int tid = threadIdx.x;
    size_t r0 = (size_t)blockIdx.x * 128;

    for (int i = tid; i < 128 * 64; i += 256) {
        int row = i >> 6, col = i & 63;
        size_t gr = r0 + row;
        float v = 0.0f;
        if (gr < N_ATOMS) {
            v = emb[(size_t)z[gr] * HID + col];
            g_h[gr * HID + col] = v;
        }
        sA[row * LDA + col] = __float2half_rn(v);
    }
    load_B(sB, g_cf1h, tid);
    __syncthreads();
    wmma_gemm(sA, sB, sC);
    __syncthreads();
    for (int i = tid; i < 128 * 32; i += 256) {
        int row = i >> 5, c2 = i & 31;
        size_t gr = r0 + row;
        if (gr < N_ATOMS) {
            __half2 hv = __floats2half2_rn(sC[row * LDC + c2 * 2], sC[row * LDC + c2 * 2 + 1]);
            *(__half2*)(g_x + gr * HID + c2 * 2) = hv;
        }
    }
}

/* --------------- message + segment-sum (interleaved a/d table) ----------- */
__device__ __forceinline__ __half2 edge_msg(unsigned long long p,
                                            const uint2* s_tab,
                                            const __half2* xbase, int lane) {
    unsigned int s_ = (unsigned int)(p >> 32);
    unsigned int lo = (unsigned int)p;
    int t_ = (int)(lo >> 16);
    __half2 f2 = __half2half2(__ushort_as_half((unsigned short)(lo & 0xffffu)));
    __half2 xv = xbase[(size_t)s_ * 32u + lane];
    uint2 ad = s_tab[t_ * 32 + lane];
    __half2 a  = *(__half2*)&ad.x;
    __half2 dd = *(__half2*)&ad.y;
    return __hmul2(__hfma2(f2, dd, a), xv);
}

__global__ void __launch_bounds__(1024, 1) aggregate_kernel(int layer) {
    extern __shared__ uint2 s_tab[];
    {
        const uint4* src = (const uint4*)(g_tbl2 + (size_t)layer * TBL_T * HID * 2);
        uint4* dst = (uint4*)s_tab;
        for (int i = threadIdx.x; i < TBL2_BYTES / 16; i += 1024) dst[i] = src[i];
    }
    __syncthreads();

    int lane = threadIdx.x & 31;
    int wib  = threadIdx.x >> 5;
    const __half2* xbase = (const __half2*)g_x;

    for (int node = blockIdx.x * 32 + wib; node < N_ATOMS; node += gridDim.x * 32) {
        int beg = g_row[node];
        int end = g_row[node + 1];
        float accx = 0.0f, accy = 0.0f;

        for (int base = beg; base < end; base += 32) {
            int cnt = min(32, end - base);
            unsigned long long pk = (lane < cnt) ? __ldcs(&g_edata[base + lane]) : 0ull;
            int j = 0;
            for (; j + 4 <= cnt; j += 4) {
                unsigned long long p0 = __shfl_sync(0xffffffffu, pk, j + 0);
                unsigned long long p1 = __shfl_sync(0xffffffffu, pk, j + 1);
                unsigned long long p2 = __shfl_sync(0xffffffffu, pk, j + 2);
                unsigned long long p3 = __shfl_sync(0xffffffffu, pk, j + 3);
                __half2 m0 = edge_msg(p0, s_tab, xbase, lane);
                __half2 m1 = edge_msg(p1, s_tab, xbase, lane);
                __half2 m2 = edge_msg(p2, s_tab, xbase, lane);
                __half2 m3 = edge_msg(p3, s_tab, xbase, lane);
                __half2 sgrp = __hadd2(__hadd2(m0, m1), __hadd2(m2, m3));
                float2 sf = __half22float2(sgrp);
                accx += sf.x;
                accy += sf.y;
            }
            for (; j < cnt; j++) {
                unsigned long long p = __shfl_sync(0xffffffffu, pk, j);
                float2 mf = __half22float2(edge_msg(p, s_tab, xbase, lane));
                accx += mf.x;
                accy += mf.y;
            }
        }
        *(__half2*)(g_aggh + (size_t)node * HID + lane * 2) = __floats2half2_rn(accx, accy);
    }
}

/* --- h += ssp(agg@W1+b1)@W2+b2 ; x = h_new@W3 (all tensor-core) ---------- */
__global__ void __launch_bounds__(256) dense_post_w(int l, int fuse_next,
                                                    const float* __restrict__ b1,
                                                    const float* __restrict__ b2) {
    extern __shared__ char sm[];
    __half* sA = (__half*)(sm + SM_A_OFF);
    __half* sB = (__half*)(sm + SM_B_OFF);
    float*  sC = (float*)(sm + SM_C_OFF);
    int tid = threadIdx.x;
    size_t r0 = (size_t)blockIdx.x * 128;

    const __half* W1 = g_cf2h + (size_t)l * HID * HID;
    const __half* W2 = g_inth + (size_t)l * HID * HID;
    const __half* W3 = g_cf1h + (size_t)(l + 1 < NLAYERS ? l + 1 : 0) * HID * HID;

    for (int i = tid; i < 128 * 32; i += 256) {
        int row = i >> 5, c2 = i & 31;
        unsigned int v = 0;
        if (r0 + row < N_ATOMS)
            v = ((const unsigned int*)g_aggh)[(r0 + row) * 32 + c2];
        *(unsigned int*)&sA[row * LDA + c2 * 2] = v;
    }
    load_B(sB, W1, tid);
    __syncthreads();
    wmma_gemm(sA, sB, sC);
    __syncthreads();

    for (int i = tid; i < 128 * 64; i += 256) {
        int row = i >> 6, col = i & 63;
        float v = ssp(sC[row * LDC + col] + __ldg(&b1[col]));
        sA[row * LDA + col] = __float2half_rn(v);
    }
    load_B(sB, W2, tid);
    __syncthreads();
    wmma_gemm(sA, sB, sC);
    __syncthreads();

    for (int i = tid; i < 128 * 64; i += 256) {
        int row = i >> 6, col = i & 63;
        size_t gr = r0 + row;
        float v = 0.0f;
        if (gr < N_ATOMS) {
            v = g_h[gr * HID + col] + sC[row * LDC + col] + __ldg(&b2[col]);
            g_h[gr * HID + col] = v;
        }
        sA[row * LDA + col] = __float2half_rn(v);
    }
    if (!fuse_next) return;

    load_B(sB, W3, tid);
    __syncthreads();
    wmma_gemm(sA, sB, sC);
    __syncthreads();
    for (int i = tid; i < 128 * 32; i += 256) {
        int row = i >> 5, c2 = i & 31;
        size_t gr = r0 + row;
        if (gr < N_ATOMS) {
            __half2 hv = __floats2half2_rn(sC[row * LDC + c2 * 2], sC[row * LDC + c2 * 2 + 1]);
            *(__half2*)(g_x + gr * HID + c2 * 2) = hv;
        }
    }
}

/* --------------- readout: per-atom MLP (64->32->1) + molecule sum -------- */
__global__ void readout_kernel(const int* __restrict__ batch,
                               const float* __restrict__ w1, const float* __restrict__ b1,
                               const float* __restrict__ w2, const float* __restrict__ b2) {
    int warp = (blockIdx.x * blockDim.x + threadIdx.x) >> 5;
    int lane = threadIdx.x & 31;
    if (warp >= N_ATOMS) return;

    float h0 = g_h[(size_t)warp * HID + lane];
    float h1 = g_h[(size_t)warp * HID + 32 + lane];

    float acc = b1[lane];
#pragma unroll
    for (int k = 0; k < 32; k++) {
        float hk = __shfl_sync(0xffffffffu, h0, k);
        acc = fmaf(hk, w1[k * 32 + lane], acc);
    }
#pragma unroll
    for (int k = 0; k < 32; k++) {
        float hk = __shfl_sync(0xffffffffu, h1, k);
        acc = fmaf(hk, w1[(32 + k) * 32 + lane], acc);
    }
    float t = ssp(acc) * w2[lane];
#pragma unroll
    for (int o = 16; o > 0; o >>= 1) t += __shfl_xor_sync(0xffffffffu, t, o);
    if (lane == 0) atomicAdd(&g_molsum[batch[warp]], t + b2[0]);
}

/* --------------- out[g] = molsum[g]*fin_w + fin_b ------------------------ */
__global__ void final_kernel(const float* __restrict__ fw, const float* __restrict__ fb,
                             float* __restrict__ out) {
    int g = blockIdx.x * blockDim.x + threadIdx.x;
    if (g < N_MOL) out[g] = g_molsum[g] * fw[0] + fb[0];
}

/* ========================================================================= */
extern "C" void kernel_launch(void* const* d_in, const int* in_sizes, int n_in,
                              void* d_out, int out_size) {
    const int*   z      = (const int*)d_in[0];
    const float* pos    = (const float*)d_in[1];
    const int*   batch  = (const int*)d_in[2];
    const int*   ei     = (const int*)d_in[3];
    const float* emb    = (const float*)d_in[4];
    const float* out_w1 = (const float*)d_in[5];
    const float* out_b1 = (const float*)d_in[6];
    const float* out_w2 = (const float*)d_in[7];
    const float* out_b2 = (const float*)d_in[8];
    const float* fin_w  = (const float*)d_in[9];
    const float* fin_b  = (const float*)d_in[10];
    const float* mlp_w1 = (const float*)d_in[11];
    const float* mlp_b1 = (const float*)d_in[12];
    const float* mlp_w2 = (const float*)d_in[13];
    const float* mlp_b2 = (const float*)d_in[14];
    const float* cf1    = (const float*)d_in[15];
    const float* cf2    = (const float*)d_in[16];
    const float* cf2b   = (const float*)d_in[17];
    const float* intw   = (const float*)d_in[18];
    const float* intb   = (const float*)d_in[19];

    (void)in_sizes; (void)n_in; (void)out_size;

    static int smem_set = 0;
    if (!smem_set) {
        cudaFuncSetAttribute(aggregate_kernel,
                             cudaFuncAttributeMaxDynamicSharedMemorySize, TBL2_BYTES);
        cudaFuncSetAttribute(dense_x_w,
                             cudaFuncAttributeMaxDynamicSharedMemorySize, SM_TOTAL);
        cudaFuncSetAttribute(dense_post_w,
                             cudaFuncAttributeMaxDynamicSharedMemorySize, SM_TOTAL);
        smem_set = 1;
    }

    zero_kernel<<<(N_ATOMS + 255) / 256, 256>>>();
    wprep_kernel<<<(NLAYERS * HID * HID + 255) / 256, 256>>>(cf1, cf2, intw);
    table_kernel<<<NLAYERS * (TBL_T / TB_TPB), 256>>>(mlp_w1, mlp_b1, mlp_w2, mlp_b2);
    pack_kernel<<<(NLAYERS * TBL_T * 32 + 255) / 256, 256>>>();
    hist_kernel<<<(N_EDGES + 255) / 256, 256>>>(ei);
    scanA_kernel<<<SCAN_BLK, 256>>>();
    scanB_kernel<<<1, 32>>>();
    scanC_kernel<<<(N_ATOMS + 255) / 256, 256>>>();
    scatter_kernel<<<(N_EDGES + 255) / 256, 256>>>(ei, pos);

    int gemm_blocks = (N_ATOMS + 127) / 128;
    int warp_blocks = (N_ATOMS * 32 + 255) / 256;

    dense_x_w<<<gemm_blocks, 256, SM_TOTAL>>>(z, emb);
    for (int l = 0; l < NLAYERS; l++) {
        aggregate_kernel<<<AGG_BLOCKS, 1024, TBL2_BYTES>>>(l);
        dense_post_w<<<gemm_blocks, 256, SM_TOTAL>>>(l, (l + 1 < NLAYERS),
                                                     cf2b + (size_t)l * HID,
                                                     intb + (size_t)l * HID);
    }

    readout_kernel<<<warp_blocks, 256>>>(batch, out_w1, out_b1, out_w2, out_b2);
    final_kernel<<<(N_MOL + 255) / 256, 256>>>(fin_w, fin_b, (float*)d_out);
}

// round 6
// speedup vs baseline: 1.9315x; 1.0657x over previous
#include <cuda_runtime.h>
#include <cuda_fp16.h>
#include <mma.h>
#include <math.h>

using namespace nvcuda;

#define N_ATOMS 100000
#define N_EDGES 3200000
#define N_MOL   2000
#define HID     64
#define NGAUSS  50
#define NLAYERS 3
#define TBL_T   512
#define TBL2_BYTES (TBL_T * HID * 4)       /* 128 KB: (a,d) interleaved fp16 */
#define DMAX    8.6603f                    /* >= 5*sqrt(3) */
#define TBL_SCALE ((float)(TBL_T-1) / DMAX)
#define LOG2F_  0.69314718055994530942f
#define PI_OVER_CUTOFF 0.31415926535897932385f
#define SCAN_BLK 98
#define AGG_BLOCKS 148
#define TB_TPB  16

/* K1 fused grid partitions */
#define WPREP_BLK 48                       /* 3*64*64/256 */
#define TBL_BLK   (NLAYERS * (TBL_T / TB_TPB))   /* 96 */
#define HIST_BLK  ((N_EDGES + 255) / 256)  /* 12500 */

/* K2 fused grid partitions */
#define PACK_BLK  ((NLAYERS * TBL_T * 32 + 255) / 256)  /* 192 */

/* K3 fused grid partitions */
#define DX_BLK    ((N_ATOMS + 127) / 128)  /* 782 */
#define SCANC_BLK ((N_ATOMS + 255) / 256)  /* 391 */

/* dense smem layout (halves padded to 72, floats to 68) */
#define LDA 72
#define LDC 68
#define SM_A_OFF  0
#define SM_B_OFF  (128 * LDA * 2)
#define SM_C_OFF  (SM_B_OFF + 64 * LDA * 2)
#define SM_TOTAL  (SM_C_OFF + 128 * LDC * 4)   /* 62464 B */

/* ------------------------- scratch (no allocs allowed) ------------------ */
__device__ int                g_hist[N_ATOMS];       /* zero-init; self-restoring */
__device__ int                g_row[N_ATOMS + 1];
__device__ int                g_cur[N_ATOMS];
__device__ int                g_part[128];
__device__ int                g_done;                /* scan ticket; self-restoring */
__device__ unsigned long long g_edata[N_EDGES];
__device__ __align__(16) __half g_traw[NLAYERS * TBL_T * HID];
__device__ __align__(16) __half g_tbl2[NLAYERS * TBL_T * HID * 2];
__device__ float              g_h[(size_t)N_ATOMS * HID];
__device__ __align__(16) __half g_x[(size_t)N_ATOMS * HID];
__device__ __align__(16) __half g_aggh[(size_t)N_ATOMS * HID];
__device__ float              g_molsum[N_MOL];       /* zero-init; self-restoring */
__device__ __align__(16) __half g_cf1h[NLAYERS * HID * HID];
__device__ __align__(16) __half g_cf2h[NLAYERS * HID * HID];
__device__ __align__(16) __half g_inth[NLAYERS * HID * HID];

__device__ __forceinline__ float ssp(float v) {
    return fmaxf(v, 0.0f) + log1pf(expf(-fabsf(v))) - LOG2F_;
}

/* =================== K1: wprep + table + hist (fused) ==================== */
__global__ void __launch_bounds__(256) k1_prep_table_hist(
        const float* __restrict__ cf1, const float* __restrict__ cf2,
        const float* __restrict__ intw,
        const float* __restrict__ w1, const float* __restrict__ b1,
        const float* __restrict__ w2, const float* __restrict__ b2,
        const int* __restrict__ ei) {
    int bid = blockIdx.x;
    int tid = threadIdx.x;

    if (bid < WPREP_BLK) {
        int i = bid * 256 + tid;
        if (i < NLAYERS * HID * HID) {
            g_cf1h[i] = __float2half_rn(cf1[i]);
            g_cf2h[i] = __float2half_rn(cf2[i]);
            g_inth[i] = __float2half_rn(intw[i]);
        }
        return;
    }
    if (bid < WPREP_BLK + TBL_BLK) {
        __shared__ float W1s[NGAUSS][HID];
        __shared__ float W2s[HID][HID];
        __shared__ float rbfs[TB_TPB][NGAUSS];
        __shared__ float tmps[TB_TPB][HID];
        int tb = bid - WPREP_BLK;
        int l = tb / (TBL_T / TB_TPB);
        int tbase = (tb % (TBL_T / TB_TPB)) * TB_TPB;

        for (int i = tid; i < NGAUSS * HID; i += 256)
            W1s[i / HID][i % HID] = w1[(size_t)l * NGAUSS * HID + i];
        for (int i = tid; i < HID * HID; i += 256)
            W2s[i >> 6][i & 63] = w2[(size_t)l * HID * HID + i];
        for (int i = tid; i < TB_TPB * NGAUSS; i += 256) {
            int tt = i / NGAUSS, k = i % NGAUSS;
            float d = (float)(tbase + tt) * (DMAX / (float)(TBL_T - 1));
            float off = (float)k * (10.0f / 49.0f);
            float u = d - off;
            const float coeff = -0.5f * (49.0f / 10.0f) * (49.0f / 10.0f);
            rbfs[tt][k] = expf(coeff * u * u);
        }
        __syncthreads();

        for (int i = tid; i < TB_TPB * HID; i += 256) {
            int tt = i >> 6, j = i & 63;
            float acc = b1[l * HID + j];
#pragma unroll
            for (int k = 0; k < NGAUSS; k++) acc = fmaf(rbfs[tt][k], W1s[k][j], acc);
            tmps[tt][j] = ssp(acc);
        }
        __syncthreads();

        for (int i = tid; i < TB_TPB * HID; i += 256) {
            int tt = i >> 6, j = i & 63;
            float acc = b2[l * HID + j];
#pragma unroll
            for (int k = 0; k < HID; k++) acc = fmaf(tmps[tt][k], W2s[k][j], acc);
            float d = (float)(tbase + tt) * (DMAX / (float)(TBL_T - 1));
            float C = 0.5f * (cosf(d * PI_OVER_CUTOFF) + 1.0f);
            g_traw[((size_t)l * TBL_T + tbase + tt) * HID + j] = __float2half_rn(acc * C);
        }
        return;
    }
    /* hist */
    int e = (bid - WPREP_BLK - TBL_BLK) * 256 + tid;
    if (e < N_EDGES) atomicAdd(&g_hist[ei[N_EDGES + e]], 1);
}

/* =================== K2: scanA(+B via last block) + pack ================= */
__global__ void __launch_bounds__(256) k2_scan_pack() {
    int bid = blockIdx.x;
    int tid = threadIdx.x;

    if (bid < SCAN_BLK) {
        __shared__ int wsum[8];
        __shared__ int s_last;
        int lane = tid & 31, wid = tid >> 5;
        int idx = bid * 1024 + tid * 4;

        int v0 = (idx + 0 < N_ATOMS) ? g_hist[idx + 0] : 0;
        int v1 = (idx + 1 < N_ATOMS) ? g_hist[idx + 1] : 0;
        int v2 = (idx + 2 < N_ATOMS) ? g_hist[idx + 2] : 0;
        int v3 = (idx + 3 < N_ATOMS) ? g_hist[idx + 3] : 0;
        /* self-restore hist to zero for next launch */
        if (idx + 0 < N_ATOMS) g_hist[idx + 0] = 0;
        if (idx + 1 < N_ATOMS) g_hist[idx + 1] = 0;
        if (idx + 2 < N_ATOMS) g_hist[idx + 2] = 0;
        if (idx + 3 < N_ATOMS) g_hist[idx + 3] = 0;

        int s = v0 + v1 + v2 + v3;
        int si = s;
#pragma unroll
        for (int o = 1; o < 32; o <<= 1) {
            int u = __shfl_up_sync(0xffffffffu, si, o);
            if (lane >= o) si += u;
        }
        if (lane == 31) wsum[wid] = si;
        __syncthreads();
        if (wid == 0 && lane < 8) {
            int w = wsum[lane];
#pragma unroll
            for (int o = 1; o < 8; o <<= 1) {
                int u = __shfl_up_sync(0x000000ffu, w, o);
                if (lane >= o) w += u;
            }
            wsum[lane] = w;
        }
        __syncthreads();
        int off = ((wid > 0) ? wsum[wid - 1] : 0) + (si - s);
        if (idx + 0 < N_ATOMS) g_row[idx + 0] = off;
        if (idx + 1 < N_ATOMS) g_row[idx + 1] = off + v0;
        if (idx + 2 < N_ATOMS) g_row[idx + 2] = off + v0 + v1;
        if (idx + 3 < N_ATOMS) g_row[idx + 3] = off + v0 + v1 + v2;
        if (tid == 0) g_part[bid] = wsum[7];

        __threadfence();
        if (tid == 0) s_last = (atomicAdd(&g_done, 1) == SCAN_BLK - 1);
        __syncthreads();
        if (s_last) {
            __threadfence();
            if (tid < 32) {
                int lane2 = tid;
                int i = lane2 * 4;
                int u0 = (i + 0 < SCAN_BLK) ? g_part[i + 0] : 0;
                int u1 = (i + 1 < SCAN_BLK) ? g_part[i + 1] : 0;
                int u2 = (i + 2 < SCAN_BLK) ? g_part[i + 2] : 0;
                int u3 = (i + 3 < SCAN_BLK) ? g_part[i + 3] : 0;
                int ss = u0 + u1 + u2 + u3;
                int ssi = ss;
#pragma unroll
                for (int o = 1; o < 32; o <<= 1) {
                    int u = __shfl_up_sync(0xffffffffu, ssi, o);
                    if (lane2 >= o) ssi += u;
                }
                int excl = ssi - ss;
                if (i + 0 < SCAN_BLK) g_part[i + 0] = excl;
                if (i + 1 < SCAN_BLK) g_part[i + 1] = excl + u0;
                if (i + 2 < SCAN_BLK) g_part[i + 2] = excl + u0 + u1;
                if (i + 3 < SCAN_BLK) g_part[i + 3] = excl + u0 + u1 + u2;
                if (lane2 == 31) g_row[N_ATOMS] = ssi;
            }
            if (tid == 0) g_done = 0;   /* self-restore ticket */
        }
        return;
    }
    /* pack raw -> interleaved (a, delta) */
    int i = (bid - SCAN_BLK) * 256 + tid;
    if (i >= NLAYERS * TBL_T * 32) return;
    int c2 = i & 31;
    int t  = (i >> 5) & (TBL_T - 1);
    int l  = i / (TBL_T * 32);
    const __half2* raw = (const __half2*)g_traw;
    __half2 a = raw[((size_t)l * TBL_T + t) * 32 + c2];
    int tn = (t + 1 < TBL_T) ? t + 1 : t;
    __half2 b = raw[((size_t)l * TBL_T + tn) * 32 + c2];
    __half2 d = __hsub2(b, a);
    __half2* dst = (__half2*)g_tbl2;
    dst[(((size_t)l * TBL_T + t) * 32 + c2) * 2 + 0] = a;
    dst[(((size_t)l * TBL_T + t) * 32 + c2) * 2 + 1] = d;
}

/* --------------- wmma 128x64x64 tile helpers ----------------------------- */
__device__ __forceinline__ void wmma_gemm(const __half* sA, const __half* sB, float* sC) {
    int w = threadIdx.x >> 5;
    wmma::fragment<wmma::accumulator, 16, 16, 16, float> c[4];
#pragma unroll
    for (int n = 0; n < 4; n++) wmma::fill_fragment(c[n], 0.0f);
#pragma unroll
    for (int k = 0; k < 4; k++) {
        wmma::fragment<wmma::matrix_a, 16, 16, 16, __half, wmma::row_major> a;
        wmma::load_matrix_sync(a, sA + (w * 16) * LDA + k * 16, LDA);
#pragma unroll
        for (int n = 0; n < 4; n++) {
            wmma::fragment<wmma::matrix_b, 16, 16, 16, __half, wmma::row_major> b;
            wmma::load_matrix_sync(b, sB + (k * 16) * LDA + n * 16, LDA);
            wmma::mma_sync(c[n], a, b, c[n]);
        }
    }
#pragma unroll
    for (int n = 0; n < 4; n++)
        wmma::store_matrix_sync(sC + (w * 16) * LDC + n * 16, c[n], LDC, wmma::mem_row_major);
}

__device__ __forceinline__ void load_B(__half* sB, const __half* W, int tid) {
    for (int i = tid; i < 64 * 32; i += 256) {
        int row = i >> 5, c2 = i & 31;
        *(unsigned int*)&sB[row * LDA + c2 * 2] = ((const unsigned int*)W)[row * 32 + c2];
    }
}

/* =================== K3: dense_x (emb@cf1[0]) + scanC ==================== */
__global__ void __launch_bounds__(256) k3_densex_scanc(const int* __restrict__ z,
                                                       const float* __restrict__ emb) {
    int bid = blockIdx.x;
    int tid = threadIdx.x;

    if (bid < DX_BLK) {
        extern __shared__ char sm[];
        __half* sA = (__half*)(sm + SM_A_OFF);
        __half* sB = (__half*)(sm + SM_B_OFF);
        float*  sC = (float*)(sm + SM_C_OFF);
        size_t r0 = (size_t)bid * 128;

        for (int i = tid; i < 128 * 64; i += 256) {
            int row = i >> 6, col = i & 63;
            size_t gr = r0 + row;
            float v = 0.0f;
            if (gr < N_ATOMS) {
                v = emb[(size_t)z[gr] * HID + col];
                g_h[gr * HID + col] = v;
            }
            sA[row * LDA + col] = __float2half_rn(v);
        }
        load_B(sB, g_cf1h, tid);
        __syncthreads();
        wmma_gemm(sA, sB, sC);
        __syncthreads();
        for (int i = tid; i < 128 * 32; i += 256) {
            int row = i >> 5, c2 = i & 31;
            size_t gr = r0 + row;
            if (gr < N_ATOMS) {
                __half2 hv = __floats2half2_rn(sC[row * LDC + c2 * 2], sC[row * LDC + c2 * 2 + 1]);
                *(__half2*)(g_x + gr * HID + c2 * 2) = hv;
            }
        }
        return;
    }
    /* scanC: finalize row offsets + cursors */
    int i = (bid - DX_BLK) * 256 + tid;
    if (i >= N_ATOMS) return;
    int v = g_row[i] + g_part[i >> 10];
    g_row[i] = v;
    g_cur[i] = v;
}

/* =================== K4: scatter (this is the profiled slot) ============= */
__global__ void scatter_kernel(const int* __restrict__ ei, const float* __restrict__ pos) {
    int e = blockIdx.x * blockDim.x + threadIdx.x;
    if (e >= N_EDGES) return;
    int s = ei[e];
    int t = ei[N_EDGES + e];
    float dx = pos[s * 3 + 0] - pos[t * 3 + 0];
    float dy = pos[s * 3 + 1] - pos[t * 3 + 1];
    float dz = pos[s * 3 + 2] - pos[t * 3 + 2];
    float d = sqrtf(dx * dx + dy * dy + dz * dz);
    float ft = d * TBL_SCALE;
    int ti = min((int)ft, TBL_T - 2);
    float f = ft - (float)ti;
    unsigned short fh = __half_as_ushort(__float2half_rn(f));
    int p = atomicAdd(&g_cur[t], 1);
    g_edata[p] = ((unsigned long long)(unsigned int)s << 32) |
                 ((unsigned int)ti << 16) | (unsigned int)fh;
}

/* --------------- message + segment-sum: 8-deep load batching ------------- */
__global__ void __launch_bounds__(1024, 1) aggregate_kernel(int layer) {
    extern __shared__ uint2 s_tab[];
    {
        const uint4* src = (const uint4*)(g_tbl2 + (size_t)layer * TBL_T * HID * 2);
        uint4* dst = (uint4*)s_tab;
        for (int i = threadIdx.x; i < TBL2_BYTES / 16; i += 1024) dst[i] = src[i];
    }
    __syncthreads();

    int lane = threadIdx.x & 31;
    int wib  = threadIdx.x >> 5;
    const __half2* xlane = (const __half2*)g_x + lane;

    for (int node = blockIdx.x * 32 + wib; node < N_ATOMS; node += gridDim.x * 32) {
        int beg = g_row[node];
        int end = g_row[node + 1];
        float accx = 0.0f, accy = 0.0f;

        for (int base = beg; base < end; base += 32) {
            int cnt = min(32, end - base);
            unsigned long long pk = (lane < cnt) ? __ldcs(&g_edata[base + lane]) : 0ull;
            unsigned plo = (unsigned)pk;
            unsigned phi = (unsigned)(pk >> 32);

            int j = 0;
            for (; j + 8 <= cnt; j += 8) {
                unsigned lo[8], sx[8];
#pragma unroll
                for (int k = 0; k < 8; k++) {
                    lo[k] = __shfl_sync(0xffffffffu, plo, j + k);
                    sx[k] = __shfl_sync(0xffffffffu, phi, j + k);
                }
                __half2 xv[8];
#pragma unroll
                for (int k = 0; k < 8; k++)
                    xv[k] = xlane[(size_t)sx[k] * 32u];
                __half2 m[8];
#pragma unroll
                for (int k = 0; k < 8; k++) {
                    uint2 ad = s_tab[(lo[k] >> 16) * 32 + lane];
                    __half2 f2 = __half2half2(__ushort_as_half((unsigned short)(lo[k] & 0xffffu)));
                    m[k] = __hmul2(__hfma2(f2, *(__half2*)&ad.y, *(__half2*)&ad.x), xv[k]);
                }
                __half2 t1 = __hadd2(__hadd2(m[0], m[1]), __hadd2(m[2], m[3]));
                __half2 t2 = __hadd2(__hadd2(m[4], m[5]), __hadd2(m[6], m[7]));
                float2 f1 = __half22float2(t1);
                float2 f2s = __half22float2(t2);
                accx += f1.x + f2s.x;
                accy += f1.y + f2s.y;
            }
            for (; j < cnt; j++) {
                unsigned lo = __shfl_sync(0xffffffffu, plo, j);
                unsigned sx = __shfl_sync(0xffffffffu, phi, j);
                uint2 ad = s_tab[(lo >> 16) * 32 + lane];
                __half2 f2 = __half2half2(__ushort_as_half((unsigned short)(lo & 0xffffu)));
                __half2 xv = xlane[(size_t)sx * 32u];
                float2 mf = __half22float2(__hmul2(__hfma2(f2, *(__half2*)&ad.y, *(__half2*)&ad.x), xv));
                accx += mf.x;
                accy += mf.y;
            }
        }
        *(__half2*)(g_aggh + (size_t)node * HID + lane * 2) = __floats2half2_rn(accx, accy);
    }
}

/* --- h += ssp(agg@W1+b1)@W2+b2 ; x = h_new@W3 (all tensor-core) ---------- */
__global__ void __launch_bounds__(256) dense_post_w(int l, int fuse_next,
                                                    const float* __restrict__ b1,
                                                    const float* __restrict__ b2) {
    extern __shared__ char sm[];
    __half* sA = (__half*)(sm + SM_A_OFF);
    __half* sB = (__half*)(sm + SM_B_OFF);
    float*  sC = (float*)(sm + SM_C_OFF);
    int tid = threadIdx.x;
    size_t r0 = (size_t)blockIdx.x * 128;

    const __half* W1 = g_cf2h + (size_t)l * HID * HID;
    const __half* W2 = g_inth + (size_t)l * HID * HID;
    const __half* W3 = g_cf1h + (size_t)(l + 1 < NLAYERS ? l + 1 : 0) * HID * HID;

    for (int i = tid; i < 128 * 32; i += 256) {
        int row = i >> 5, c2 = i & 31;
        unsigned int v = 0;
        if (r0 + row < N_ATOMS)
            v = ((const unsigned int*)g_aggh)[(r0 + row) * 32 + c2];
        *(unsigned int*)&sA[row * LDA + c2 * 2] = v;
    }
    load_B(sB, W1, tid);
    __syncthreads();
    wmma_gemm(sA, sB, sC);
    __syncthreads();

    for (int i = tid; i < 128 * 64; i += 256) {
        int row = i >> 6, col = i & 63;
        float v = ssp(sC[row * LDC + col] + __ldg(&b1[col]));
        sA[row * LDA + col] = __float2half_rn(v);
    }
    load_B(sB, W2, tid);
    __syncthreads();
    wmma_gemm(sA, sB, sC);
    __syncthreads();

    for (int i = tid; i < 128 * 64; i += 256) {
        int row = i >> 6, col = i & 63;
        size_t gr = r0 + row;
        float v = 0.0f;
        if (gr < N_ATOMS) {
            v = g_h[gr * HID + col] + sC[row * LDC + col] + __ldg(&b2[col]);
            g_h[gr * HID + col] = v;
        }
        sA[row * LDA + col] = __float2half_rn(v);
    }
    if (!fuse_next) return;

    load_B(sB, W3, tid);
    __syncthreads();
    wmma_gemm(sA, sB, sC);
    __syncthreads();
    for (int i = tid; i < 128 * 32; i += 256) {
        int row = i >> 5, c2 = i & 31;
        size_t gr = r0 + row;
        if (gr < N_ATOMS) {
            __half2 hv = __floats2half2_rn(sC[row * LDC + c2 * 2], sC[row * LDC + c2 * 2 + 1]);
            *(__half2*)(g_x + gr * HID + c2 * 2) = hv;
        }
    }
}

/* --------------- readout: per-atom MLP (64->32->1) + molecule sum -------- */
__global__ void readout_kernel(const int* __restrict__ batch,
                               const float* __restrict__ w1, const float* __restrict__ b1,
                               const float* __restrict__ w2, const float* __restrict__ b2) {
    int warp = (blockIdx.x * blockDim.x + threadIdx.x) >> 5;
    int lane = threadIdx.x & 31;
    if (warp >= N_ATOMS) return;

    float h0 = g_h[(size_t)warp * HID + lane];
    float h1 = g_h[(size_t)warp * HID + 32 + lane];

    float acc = b1[lane];
#pragma unroll
    for (int k = 0; k < 32; k++) {
        float hk = __shfl_sync(0xffffffffu, h0, k);
        acc = fmaf(hk, w1[k * 32 + lane], acc);
    }
#pragma unroll
    for (int k = 0; k < 32; k++) {
        float hk = __shfl_sync(0xffffffffu, h1, k);
        acc = fmaf(hk, w1[(32 + k) * 32 + lane], acc);
    }
    float t = ssp(acc) * w2[lane];
#pragma unroll
    for (int o = 16; o > 0; o >>= 1) t += __shfl_xor_sync(0xffffffffu, t, o);
    if (lane == 0) atomicAdd(&g_molsum[batch[warp]], t + b2[0]);
}

/* ------- out[g] = molsum[g]*fin_w + fin_b ; self-restore molsum ---------- */
__global__ void final_kernel(const float* __restrict__ fw, const float* __restrict__ fb,
                             float* __restrict__ out) {
    int g = blockIdx.x * blockDim.x + threadIdx.x;
    if (g < N_MOL) {
        float v = g_molsum[g];
        out[g] = v * fw[0] + fb[0];
        g_molsum[g] = 0.0f;
    }
}

/* ========================================================================= */
extern "C" void kernel_launch(void* const* d_in, const int* in_sizes, int n_in,
                              void* d_out, int out_size) {
    const int*   z      = (const int*)d_in[0];
    const float* pos    = (const float*)d_in[1];
    const int*   batch  = (const int*)d_in[2];
    const int*   ei     = (const int*)d_in[3];
    const float* emb    = (const float*)d_in[4];
    const float* out_w1 = (const float*)d_in[5];
    const float* out_b1 = (const float*)d_in[6];
    const float* out_w2 = (const float*)d_in[7];
    const float* out_b2 = (const float*)d_in[8];
    const float* fin_w  = (const float*)d_in[9];
    const float* fin_b  = (const float*)d_in[10];
    const float* mlp_w1 = (const float*)d_in[11];
    const float* mlp_b1 = (const float*)d_in[12];
    const float* mlp_w2 = (const float*)d_in[13];
    const float* mlp_b2 = (const float*)d_in[14];
    const float* cf1    = (const float*)d_in[15];
    const float* cf2    = (const float*)d_in[16];
    const float* cf2b   = (const float*)d_in[17];
    const float* intw   = (const float*)d_in[18];
    const float* intb   = (const float*)d_in[19];

    (void)in_sizes; (void)n_in; (void)out_size; (void)cf1;

    cudaFuncSetAttribute(aggregate_kernel,
                         cudaFuncAttributeMaxDynamicSharedMemorySize, TBL2_BYTES);
    cudaFuncSetAttribute(k3_densex_scanc,
                         cudaFuncAttributeMaxDynamicSharedMemorySize, SM_TOTAL);
    cudaFuncSetAttribute(dense_post_w,
                         cudaFuncAttributeMaxDynamicSharedMemorySize, SM_TOTAL);

    /* K1: weight fp16 prep + filter table + dst histogram */
    k1_prep_table_hist<<<WPREP_BLK + TBL_BLK + HIST_BLK, 256>>>(
        cf1, cf2, intw, mlp_w1, mlp_b1, mlp_w2, mlp_b2, ei);
    /* K2: block scan (+partials scan in last block) + table pack */
    k2_scan_pack<<<SCAN_BLK + PACK_BLK, 256>>>();
    /* K3: x = emb[z] @ cf1[0]  +  scanC offsets/cursors */
    k3_densex_scanc<<<DX_BLK + SCANC_BLK, 256, SM_TOTAL>>>(z, emb);
    /* K4: scatter (profiled slot) */
    scatter_kernel<<<(N_EDGES + 255) / 256, 256>>>(ei, pos);

    for (int l = 0; l < NLAYERS; l++) {
        aggregate_kernel<<<AGG_BLOCKS, 1024, TBL2_BYTES>>>(l);
        dense_post_w<<<DX_BLK, 256, SM_TOTAL>>>(l, (l + 1 < NLAYERS),
                                                cf2b + (size_t)l * HID,
                                                intb + (size_t)l * HID);
    }

    int warp_blocks = (N_ATOMS * 32 + 255) / 256;
    readout_kernel<<<warp_blocks, 256>>>(batch, out_w1, out_b1, out_w2, out_b2);
    final_kernel<<<(N_MOL + 255) / 256, 256>>>(fin_w, fin_b, (float*)d_out);
}

// round 7
// speedup vs baseline: 1.9575x; 1.0134x over previous
#include <cuda_runtime.h>
#include <cuda_fp16.h>
#include <mma.h>
#include <math.h>

using namespace nvcuda;

#define N_ATOMS 100000
#define N_EDGES 3200000
#define N_MOL   2000
#define HID     64
#define NGAUSS  50
#define NLAYERS 3
#define TBL_T   512
#define TBL2_BYTES (TBL_T * HID * 4)       /* 128 KB: (a,d) interleaved fp16 */
#define DMAX    8.6603f                    /* >= 5*sqrt(3) */
#define TBL_SCALE ((float)(TBL_T-1) / DMAX)
#define LOG2F_  0.69314718055994530942f
#define PI_OVER_CUTOFF 0.31415926535897932385f
#define SCAN_BLK 98
#define AGG_BLOCKS 148
#define TB_TPB  16

/* K1 fused grid partitions */
#define WPREP_BLK 48                       /* 3*64*64/256 */
#define POS_BLK   ((N_ATOMS + 255) / 256)  /* 391 */
#define TBL_BLK   (NLAYERS * (TBL_T / TB_TPB))   /* 96 */
#define HIST_BLK  ((N_EDGES + 255) / 256)  /* 12500 */

/* K2 fused grid partitions */
#define PACK_BLK  ((NLAYERS * TBL_T * 32 + 255) / 256)  /* 192 */
#define DX_BLK    ((N_ATOMS + 127) / 128)  /* 782 */
#define SCANC_BLK ((N_ATOMS + 255) / 256)  /* 391 */

/* dense smem layout (halves padded to 72, floats to 68) */
#define LDA 72
#define LDC 68
#define SM_A_OFF  0
#define SM_B_OFF  (128 * LDA * 2)
#define SM_C_OFF  (SM_B_OFF + 64 * LDA * 2)
#define SM_TOTAL  (SM_C_OFF + 128 * LDC * 4)   /* 62464 B */

/* ------------------------- scratch (no allocs allowed) ------------------ */
__device__ int                g_hist[N_ATOMS];       /* zero-init; self-restoring */
__device__ int                g_row[N_ATOMS + 1];
__device__ int                g_cur[N_ATOMS];
__device__ int                g_part[128];
__device__ int                g_done;                /* scan ticket; self-restoring */
__device__ int                g_flag;                /* scanB-done flag; reset in K3 */
__device__ unsigned long long g_edata[N_EDGES];
__device__ float4             g_pos4[N_ATOMS];
__device__ __align__(16)  __half g_traw[NLAYERS * TBL_T * HID];
__device__ __align__(16)  __half g_tbl2[NLAYERS * TBL_T * HID * 2];
__device__ float              g_h[(size_t)N_ATOMS * HID];
__device__ __align__(128) __half g_x[(size_t)N_ATOMS * HID];
__device__ __align__(128) __half g_aggh[(size_t)N_ATOMS * HID];
__device__ float              g_molsum[N_MOL];       /* zero-init; self-restoring */
__device__ __align__(16) __half g_cf1h[NLAYERS * HID * HID];
__device__ __align__(16) __half g_cf2h[NLAYERS * HID * HID];
__device__ __align__(16) __half g_inth[NLAYERS * HID * HID];

__device__ __forceinline__ float ssp(float v) {
    return fmaxf(v, 0.0f) + log1pf(expf(-fabsf(v))) - LOG2F_;
}

/* --------------- wmma 128x64x64 tile helpers ----------------------------- */
__device__ __forceinline__ void wmma_gemm(const __half* sA, const __half* sB, float* sC) {
    int w = threadIdx.x >> 5;
    wmma::fragment<wmma::accumulator, 16, 16, 16, float> c[4];
#pragma unroll
    for (int n = 0; n < 4; n++) wmma::fill_fragment(c[n], 0.0f);
#pragma unroll
    for (int k = 0; k < 4; k++) {
        wmma::fragment<wmma::matrix_a, 16, 16, 16, __half, wmma::row_major> a;
        wmma::load_matrix_sync(a, sA + (w * 16) * LDA + k * 16, LDA);
#pragma unroll
        for (int n = 0; n < 4; n++) {
            wmma::fragment<wmma::matrix_b, 16, 16, 16, __half, wmma::row_major> b;
            wmma::load_matrix_sync(b, sB + (k * 16) * LDA + n * 16, LDA);
            wmma::mma_sync(c[n], a, b, c[n]);
        }
    }
#pragma unroll
    for (int n = 0; n < 4; n++)
        wmma::store_matrix_sync(sC + (w * 16) * LDC + n * 16, c[n], LDC, wmma::mem_row_major);
}

__device__ __forceinline__ void load_B(__half* sB, const __half* W, int tid) {
    for (int i = tid; i < 64 * 32; i += 256) {
        int row = i >> 5, c2 = i & 31;
        *(unsigned int*)&sB[row * LDA + c2 * 2] = ((const unsigned int*)W)[row * 32 + c2];
    }
}

/* =========== K1: wprep + pos4 repack + table + hist (fused) ============== */
__global__ void __launch_bounds__(256) k1_prep_table_hist(
        const float* __restrict__ cf1, const float* __restrict__ cf2,
        const float* __restrict__ intw,
        const float* __restrict__ w1, const float* __restrict__ b1,
        const float* __restrict__ w2, const float* __restrict__ b2,
        const int* __restrict__ ei, const float* __restrict__ pos) {
    int bid = blockIdx.x;
    int tid = threadIdx.x;

    if (bid < WPREP_BLK) {
        int i = bid * 256 + tid;
        if (i < NLAYERS * HID * HID) {
            g_cf1h[i] = __float2half_rn(cf1[i]);
            g_cf2h[i] = __float2half_rn(cf2[i]);
            g_inth[i] = __float2half_rn(intw[i]);
        }
        return;
    }
    if (bid < WPREP_BLK + POS_BLK) {
        int i = (bid - WPREP_BLK) * 256 + tid;
        if (i < N_ATOMS)
            g_pos4[i] = make_float4(pos[3 * i], pos[3 * i + 1], pos[3 * i + 2], 0.0f);
        return;
    }
    if (bid < WPREP_BLK + POS_BLK + TBL_BLK) {
        __shared__ float W1s[NGAUSS][HID];
        __shared__ float W2s[HID][HID];
        __shared__ float rbfs[TB_TPB][NGAUSS];
        __shared__ float tmps[TB_TPB][HID];
        int tb = bid - WPREP_BLK - POS_BLK;
        int l = tb / (TBL_T / TB_TPB);
        int tbase = (tb % (TBL_T / TB_TPB)) * TB_TPB;

        for (int i = tid; i < NGAUSS * HID; i += 256)
            W1s[i / HID][i % HID] = w1[(size_t)l * NGAUSS * HID + i];
        for (int i = tid; i < HID * HID; i += 256)
            W2s[i >> 6][i & 63] = w2[(size_t)l * HID * HID + i];
        for (int i = tid; i < TB_TPB * NGAUSS; i += 256) {
            int tt = i / NGAUSS, k = i % NGAUSS;
            float d = (float)(tbase + tt) * (DMAX / (float)(TBL_T - 1));
            float off = (float)k * (10.0f / 49.0f);
            float u = d - off;
            const float coeff = -0.5f * (49.0f / 10.0f) * (49.0f / 10.0f);
            rbfs[tt][k] = expf(coeff * u * u);
        }
        __syncthreads();

        for (int i = tid; i < TB_TPB * HID; i += 256) {
            int tt = i >> 6, j = i & 63;
            float acc = b1[l * HID + j];
#pragma unroll
            for (int k = 0; k < NGAUSS; k++) acc = fmaf(rbfs[tt][k], W1s[k][j], acc);
            tmps[tt][j] = ssp(acc);
        }
        __syncthreads();

        for (int i = tid; i < TB_TPB * HID; i += 256) {
            int tt = i >> 6, j = i & 63;
            float acc = b2[l * HID + j];
#pragma unroll
            for (int k = 0; k < HID; k++) acc = fmaf(tmps[tt][k], W2s[k][j], acc);
            float d = (float)(tbase + tt) * (DMAX / (float)(TBL_T - 1));
            float C = 0.5f * (cosf(d * PI_OVER_CUTOFF) + 1.0f);
            g_traw[((size_t)l * TBL_T + tbase + tt) * HID + j] = __float2half_rn(acc * C);
        }
        return;
    }
    /* hist */
    int e = (bid - WPREP_BLK - POS_BLK - TBL_BLK) * 256 + tid;
    if (e < N_EDGES) atomicAdd(&g_hist[ei[N_EDGES + e]], 1);
}

/* ====== K2: scanA(+B last block) + pack + dense_x + scanC(spin) ========== */
__global__ void __launch_bounds__(256) k2_scan_pack_densex(const int* __restrict__ z,
                                                           const float* __restrict__ emb) {
    int bid = blockIdx.x;
    int tid = threadIdx.x;

    if (bid < SCAN_BLK) {
        __shared__ int wsum[8];
        __shared__ int s_last;
        int lane = tid & 31, wid = tid >> 5;
        int idx = bid * 1024 + tid * 4;

        int v0 = (idx + 0 < N_ATOMS) ? g_hist[idx + 0] : 0;
        int v1 = (idx + 1 < N_ATOMS) ? g_hist[idx + 1] : 0;
        int v2 = (idx + 2 < N_ATOMS) ? g_hist[idx + 2] : 0;
        int v3 = (idx + 3 < N_ATOMS) ? g_hist[idx + 3] : 0;
        if (idx + 0 < N_ATOMS) g_hist[idx + 0] = 0;
        if (idx + 1 < N_ATOMS) g_hist[idx + 1] = 0;
        if (idx + 2 < N_ATOMS) g_hist[idx + 2] = 0;
        if (idx + 3 < N_ATOMS) g_hist[idx + 3] = 0;

        int s = v0 + v1 + v2 + v3;
        int si = s;
#pragma unroll
        for (int o = 1; o < 32; o <<= 1) {
            int u = __shfl_up_sync(0xffffffffu, si, o);
            if (lane >= o) si += u;
        }
        if (lane == 31) wsum[wid] = si;
        __syncthreads();
        if (wid == 0 && lane < 8) {
            int w = wsum[lane];
#pragma unroll
            for (int o = 1; o < 8; o <<= 1) {
                int u = __shfl_up_sync(0x000000ffu, w, o);
                if (lane >= o) w += u;
            }
            wsum[lane] = w;
        }
        __syncthreads();
        int off = ((wid > 0) ? wsum[wid - 1] : 0) + (si - s);
        if (idx + 0 < N_ATOMS) g_row[idx + 0] = off;
        if (idx + 1 < N_ATOMS) g_row[idx + 1] = off + v0;
        if (idx + 2 < N_ATOMS) g_row[idx + 2] = off + v0 + v1;
        if (idx + 3 < N_ATOMS) g_row[idx + 3] = off + v0 + v1 + v2;
        if (tid == 0) g_part[bid] = wsum[7];

        __threadfence();
        if (tid == 0) s_last = (atomicAdd(&g_done, 1) == SCAN_BLK - 1);
        __syncthreads();
        if (s_last) {
            __threadfence();
            if (tid < 32) {
                int lane2 = tid;
                int i = lane2 * 4;
                int u0 = (i + 0 < SCAN_BLK) ? g_part[i + 0] : 0;
                int u1 = (i + 1 < SCAN_BLK) ? g_part[i + 1] : 0;
                int u2 = (i + 2 < SCAN_BLK) ? g_part[i + 2] : 0;
                int u3 = (i + 3 < SCAN_BLK) ? g_part[i + 3] : 0;
                int ss = u0 + u1 + u2 + u3;
                int ssi = ss;
#pragma unroll
                for (int o = 1; o < 32; o <<= 1) {
                    int u = __shfl_up_sync(0xffffffffu, ssi, o);
                    if (lane2 >= o) ssi += u;
                }
                int excl = ssi - ss;
                if (i + 0 < SCAN_BLK) g_part[i + 0] = excl;
                if (i + 1 < SCAN_BLK) g_part[i + 1] = excl + u0;
                if (i + 2 < SCAN_BLK) g_part[i + 2] = excl + u0 + u1;
                if (i + 3 < SCAN_BLK) g_part[i + 3] = excl + u0 + u1 + u2;
                if (lane2 == 31) g_row[N_ATOMS] = ssi;
                __syncwarp();
                if (lane2 == 0) {
                    g_done = 0;            /* self-restore ticket */
                    __threadfence();
                    g_flag = 1;            /* release scanC blocks */
                }
            }
        }
        return;
    }
    if (bid < SCAN_BLK + PACK_BLK) {
        /* pack raw -> interleaved (a, delta) */
        int i = (bid - SCAN_BLK) * 256 + tid;
        if (i >= NLAYERS * TBL_T * 32) return;
        int c2 = i & 31;
        int t  = (i >> 5) & (TBL_T - 1);
        int l  = i / (TBL_T * 32);
        const __half2* raw = (const __half2*)g_traw;
        __half2 a = raw[((size_t)l * TBL_T + t) * 32 + c2];
        int tn = (t + 1 < TBL_T) ? t + 1 : t;
        __half2 b = raw[((size_t)l * TBL_T + tn) * 32 + c2];
        __half2 d = __hsub2(b, a);
        __half2* dst = (__half2*)g_tbl2;
        dst[(((size_t)l * TBL_T + t) * 32 + c2) * 2 + 0] = a;
        dst[(((size_t)l * TBL_T + t) * 32 + c2) * 2 + 1] = d;
        return;
    }
    if (bid < SCAN_BLK + PACK_BLK + DX_BLK) {
        /* dense_x: x = emb[z] @ cf1[0]; also init g_h */
        extern __shared__ char sm[];
        __half* sA = (__half*)(sm + SM_A_OFF);
        __half* sB = (__half*)(sm + SM_B_OFF);
        float*  sC = (float*)(sm + SM_C_OFF);
        size_t r0 = (size_t)(bid - SCAN_BLK - PACK_BLK) * 128;

        for (int i = tid; i < 128 * 64; i += 256) {
            int row = i >> 6, col = i & 63;
            size_t gr = r0 + row;
            float v = 0.0f;
            if (gr < N_ATOMS) {
                v = emb[(size_t)z[gr] * HID + col];
                g_h[gr * HID + col] = v;
            }
            sA[row * LDA + col] = __float2half_rn(v);
        }
        load_B(sB, g_cf1h, tid);
        __syncthreads();
        wmma_gemm(sA, sB, sC);
        __syncthreads();
        for (int i = tid; i < 128 * 32; i += 256) {
            int row = i >> 5, c2 = i & 31;
            size_t gr = r0 + row;
            if (gr < N_ATOMS) {
                __half2 hv = __floats2half2_rn(sC[row * LDC + c2 * 2], sC[row * LDC + c2 * 2 + 1]);
                *(__half2*)(g_x + gr * HID + c2 * 2) = hv;
            }
        }
        return;
    }
    /* scanC: wait for scanB, then finalize offsets + cursors */
    if (tid == 0) {
        while (!*((volatile int*)&g_flag)) __nanosleep(64);
    }
    __syncthreads();
    __threadfence();
    int i = (bid - SCAN_BLK - PACK_BLK - DX_BLK) * 256 + tid;
    if (i >= N_ATOMS) return;
    int v = g_row[i] + g_part[i >> 10];
    g_row[i] = v;
    g_cur[i] = v;
}

/* =================== K3: scatter ========================================= */
__global__ void scatter_kernel(const int* __restrict__ ei) {
    int e = blockIdx.x * blockDim.x + threadIdx.x;
    if (e == 0) g_flag = 0;                /* self-restore K2's release flag */
    if (e >= N_EDGES) return;
    int s = ei[e];
    int t = ei[N_EDGES + e];
    float4 ps = g_pos4[s];
    float4 pt = g_pos4[t];
    float dx = ps.x - pt.x, dy = ps.y - pt.y, dz = ps.z - pt.z;
    float d = sqrtf(dx * dx + dy * dy + dz * dz);
    float ft = d * TBL_SCALE;
    int ti = min((int)ft, TBL_T - 2);
    float f = ft - (float)ti;
    unsigned short fh = __half_as_ushort(__float2half_rn(f));
    int p = atomicAdd(&g_cur[t], 1);
    g_edata[p] = ((unsigned long long)(unsigned int)s << 32) |
                 ((unsigned int)ti << 16) | (unsigned int)fh;
}

/* ====== K4: message + segment-sum (PROFILED SLOT) ======================== */
__global__ void __launch_bounds__(1024, 1) aggregate_kernel(int layer) {
    extern __shared__ uint2 s_tab[];
    {
        const uint4* src = (const uint4*)(g_tbl2 + (size_t)layer * TBL_T * HID * 2);
        uint4* dst = (uint4*)s_tab;
        for (int i = threadIdx.x; i < TBL2_BYTES / 16; i += 1024) dst[i] = src[i];
    }
    __syncthreads();

    int lane = threadIdx.x & 31;
    int wib  = threadIdx.x >> 5;
    const __half2* xlane = (const __half2*)g_x + lane;

    for (int node = blockIdx.x * 32 + wib; node < N_ATOMS; node += gridDim.x * 32) {
        int beg = g_row[node];
        int end = g_row[node + 1];
        float accx = 0.0f, accy = 0.0f;

        for (int base = beg; base < end; base += 32) {
            int cnt = min(32, end - base);
            unsigned long long pk = (lane < cnt) ? __ldcs(&g_edata[base + lane]) : 0ull;
            unsigned plo = (unsigned)pk;
            unsigned phi = (unsigned)(pk >> 32);

            int j = 0;
            for (; j + 8 <= cnt; j += 8) {
                unsigned lo[8], sx[8];
#pragma unroll
                for (int k = 0; k < 8; k++) {
                    lo[k] = __shfl_sync(0xffffffffu, plo, j + k);
                    sx[k] = __shfl_sync(0xffffffffu, phi, j + k);
                }
                __half2 xv[8];
#pragma unroll
                for (int k = 0; k < 8; k++)
                    xv[k] = xlane[(size_t)sx[k] * 32u];
                __half2 m[8];
#pragma unroll
                for (int k = 0; k < 8; k++) {
                    uint2 ad = s_tab[(lo[k] >> 16) * 32 + lane];
                    __half2 f2 = __half2half2(__ushort_as_half((unsigned short)(lo[k] & 0xffffu)));
                    m[k] = __hmul2(__hfma2(f2, *(__half2*)&ad.y, *(__half2*)&ad.x), xv[k]);
                }
                __half2 t1 = __hadd2(__hadd2(m[0], m[1]), __hadd2(m[2], m[3]));
                __half2 t2 = __hadd2(__hadd2(m[4], m[5]), __hadd2(m[6], m[7]));
                float2 f1 = __half22float2(t1);
                float2 f2s = __half22float2(t2);
                accx += f1.x + f2s.x;
                accy += f1.y + f2s.y;
            }
            for (; j < cnt; j++) {
                unsigned lo = __shfl_sync(0xffffffffu, plo, j);
                unsigned sx = __shfl_sync(0xffffffffu, phi, j);
                uint2 ad = s_tab[(lo >> 16) * 32 + lane];
                __half2 f2 = __half2half2(__ushort_as_half((unsigned short)(lo & 0xffffu)));
                __half2 xv = xlane[(size_t)sx * 32u];
                float2 mf = __half22float2(__hmul2(__hfma2(f2, *(__half2*)&ad.y, *(__half2*)&ad.x), xv));
                accx += mf.x;
                accy += mf.y;
            }
        }
        *(__half2*)(g_aggh + (size_t)node * HID + lane * 2) = __floats2half2_rn(accx, accy);
    }
}

/* --- h += ssp(agg@W1+b1)@W2+b2 ; x = h_new@W3 (all tensor-core) ---------- */
__global__ void __launch_bounds__(256) dense_post_w(int l, int fuse_next,
                                                    const float* __restrict__ b1,
                                                    const float* __restrict__ b2) {
    extern __shared__ char sm[];
    __half* sA = (__half*)(sm + SM_A_OFF);
    __half* sB = (__half*)(sm + SM_B_OFF);
    float*  sC = (float*)(sm + SM_C_OFF);
    int tid = threadIdx.x;
    size_t r0 = (size_t)blockIdx.x * 128;

    const __half* W1 = g_cf2h + (size_t)l * HID * HID;
    const __half* W2 = g_inth + (size_t)l * HID * HID;
    const __half* W3 = g_cf1h + (size_t)(l + 1 < NLAYERS ? l + 1 : 0) * HID * HID;

    for (int i = tid; i < 128 * 32; i += 256) {
        int row = i >> 5, c2 = i & 31;
        unsigned int v = 0;
        if (r0 + row < N_ATOMS)
            v = ((const unsigned int*)g_aggh)[(r0 + row) * 32 + c2];
        *(unsigned int*)&sA[row * LDA + c2 * 2] = v;
    }
    load_B(sB, W1, tid);
    __syncthreads();
    wmma_gemm(sA, sB, sC);
    __syncthreads();

    for (int i = tid; i < 128 * 64; i += 256) {
        int row = i >> 6, col = i & 63;
        float v = ssp(sC[row * LDC + col] + __ldg(&b1[col]));
        sA[row * LDA + col] = __float2half_rn(v);
    }
    load_B(sB, W2, tid);
    __syncthreads();
    wmma_gemm(sA, sB, sC);
    __syncthreads();

    for (int i = tid; i < 128 * 64; i += 256) {
        int row = i >> 6, col = i & 63;
        size_t gr = r0 + row;
        float v = 0.0f;
        if (gr < N_ATOMS) {
            v = g_h[gr * HID + col] + sC[row * LDC + col] + __ldg(&b2[col]);
            g_h[gr * HID + col] = v;
        }
        sA[row * LDA + col] = __float2half_rn(v);
    }
    if (!fuse_next) return;

    load_B(sB, W3, tid);
    __syncthreads();
    wmma_gemm(sA, sB, sC);
    __syncthreads();
    for (int i = tid; i < 128 * 32; i += 256) {
        int row = i >> 5, c2 = i & 31;
        size_t gr = r0 + row;
        if (gr < N_ATOMS) {
            __half2 hv = __floats2half2_rn(sC[row * LDC + c2 * 2], sC[row * LDC + c2 * 2 + 1]);
            *(__half2*)(g_x + gr * HID + c2 * 2) = hv;
        }
    }
}

/* --------------- readout: per-atom MLP (64->32->1) + molecule sum -------- */
__global__ void readout_kernel(const int* __restrict__ batch,
                               const float* __restrict__ w1, const float* __restrict__ b1,
                               const float* __restrict__ w2, const float* __restrict__ b2) {
    int warp = (blockIdx.x * blockDim.x + threadIdx.x) >> 5;
    int lane = threadIdx.x & 31;
    if (warp >= N_ATOMS) return;

    float h0 = g_h[(size_t)warp * HID + lane];
    float h1 = g_h[(size_t)warp * HID + 32 + lane];

    float acc = b1[lane];
#pragma unroll
    for (int k = 0; k < 32; k++) {
        float hk = __shfl_sync(0xffffffffu, h0, k);
        acc = fmaf(hk, w1[k * 32 + lane], acc);
    }
#pragma unroll
    for (int k = 0; k < 32; k++) {
        float hk = __shfl_sync(0xffffffffu, h1, k);
        acc = fmaf(hk, w1[(32 + k) * 32 + lane], acc);
    }
    float t = ssp(acc) * w2[lane];
#pragma unroll
    for (int o = 16; o > 0; o >>= 1) t += __shfl_xor_sync(0xffffffffu, t, o);
    if (lane == 0) atomicAdd(&g_molsum[batch[warp]], t + b2[0]);
}

/* ------- out[g] = molsum[g]*fin_w + fin_b ; self-restore molsum ---------- */
__global__ void final_kernel(const float* __restrict__ fw, const float* __restrict__ fb,
                             float* __restrict__ out) {
    int g = blockIdx.x * blockDim.x + threadIdx.x;
    if (g < N_MOL) {
        float v = g_molsum[g];
        out[g] = v * fw[0] + fb[0];
        g_molsum[g] = 0.0f;
    }
}

/* ========================================================================= */
extern "C" void kernel_launch(void* const* d_in, const int* in_sizes, int n_in,
                              void* d_out, int out_size) {
    const int*   z      = (const int*)d_in[0];
    const float* pos    = (const float*)d_in[1];
    const int*   batch  = (const int*)d_in[2];
    const int*   ei     = (const int*)d_in[3];
    const float* emb    = (const float*)d_in[4];
    const float* out_w1 = (const float*)d_in[5];
    const float* out_b1 = (const float*)d_in[6];
    const float* out_w2 = (const float*)d_in[7];
    const float* out_b2 = (const float*)d_in[8];
    const float* fin_w  = (const float*)d_in[9];
    const float* fin_b  = (const float*)d_in[10];
    const float* mlp_w1 = (const float*)d_in[11];
    const float* mlp_b1 = (const float*)d_in[12];
    const float* mlp_w2 = (const float*)d_in[13];
    const float* mlp_b2 = (const float*)d_in[14];
    const float* cf1    = (const float*)d_in[15];
    const float* cf2    = (const float*)d_in[16];
    const float* cf2b   = (const float*)d_in[17];
    const float* intw   = (const float*)d_in[18];
    const float* intb   = (const float*)d_in[19];

    (void)in_sizes; (void)n_in; (void)out_size;

    cudaFuncSetAttribute(aggregate_kernel,
                         cudaFuncAttributeMaxDynamicSharedMemorySize, TBL2_BYTES);
    cudaFuncSetAttribute(k2_scan_pack_densex,
                         cudaFuncAttributeMaxDynamicSharedMemorySize, SM_TOTAL);
    cudaFuncSetAttribute(dense_post_w,
                         cudaFuncAttributeMaxDynamicSharedMemorySize, SM_TOTAL);

    /* K1: weight fp16 prep + pos float4 repack + filter table + histogram */
    k1_prep_table_hist<<<WPREP_BLK + POS_BLK + TBL_BLK + HIST_BLK, 256>>>(
        cf1, cf2, intw, mlp_w1, mlp_b1, mlp_w2, mlp_b2, ei, pos);
    /* K2: scan (+partials in last block) + pack + dense_x + scanC(spin) */
    k2_scan_pack_densex<<<SCAN_BLK + PACK_BLK + DX_BLK + SCANC_BLK, 256, SM_TOTAL>>>(z, emb);
    /* K3: scatter */
    scatter_kernel<<<(N_EDGES + 255) / 256, 256>>>(ei);

    for (int l = 0; l < NLAYERS; l++) {
        aggregate_kernel<<<AGG_BLOCKS, 1024, TBL2_BYTES>>>(l);   /* l=0 is launch #4 */
        dense_post_w<<<DX_BLK, 256, SM_TOTAL>>>(l, (l + 1 < NLAYERS),
                                                cf2b + (size_t)l * HID,
                                                intb + (size_t)l * HID);
    }

    int warp_blocks = (N_ATOMS * 32 + 255) / 256;
    readout_kernel<<<warp_blocks, 256>>>(batch, out_w1, out_b1, out_w2, out_b2);
    final_kernel<<<(N_MOL + 255) / 256, 256>>>(fin_w, fin_b, (float*)d_out);
}

// round 8
// speedup vs baseline: 2.0563x; 1.0505x over previous
#include <cuda_runtime.h>
#include <cuda_fp16.h>
#include <mma.h>
#include <math.h>

using namespace nvcuda;

#define N_ATOMS 100000
#define N_EDGES 3200000
#define N_MOL   2000
#define HID     64
#define NGAUSS  50
#define NLAYERS 3
#define TBL_T   512
#define TBL2_BYTES (TBL_T * HID * 4)       /* 128 KB: (a, delta/64) interleaved */
#define DMAX    8.6603f                    /* >= 5*sqrt(3) */
#define TBL_SCALE ((float)(TBL_T-1) / DMAX)
#define TBL_SCALE64 (TBL_SCALE * 64.0f)
#define TI6_MAX ((TBL_T - 2) * 64 + 63)    /* 32703 */
#define LOG2F_  0.69314718055994530942f
#define PI_OVER_CUTOFF 0.31415926535897932385f
#define SCAN_BLK 98
#define AGG_BLOCKS 148
#define TB_TPB  16

/* K1 fused grid partitions */
#define WPREP_BLK 48
#define POS_BLK   ((N_ATOMS + 255) / 256)
#define TBL_BLK   (NLAYERS * (TBL_T / TB_TPB))
#define HIST_BLK  ((N_EDGES + 255) / 256)

/* K2 fused grid partitions */
#define PACK_BLK  ((NLAYERS * TBL_T * 32 + 255) / 256)
#define DX_BLK    ((N_ATOMS + 127) / 128)
#define SCANC_BLK ((N_ATOMS + 255) / 256)

/* dense smem layout */
#define LDA 72
#define LDC 68
#define SM_A_OFF  0
#define SM_B_OFF  (128 * LDA * 2)
#define SM_C_OFF  (SM_B_OFF + 64 * LDA * 2)
#define SM_TOTAL  (SM_C_OFF + 128 * LDC * 4)

/* ------------------------- scratch (no allocs allowed) ------------------ */
__device__ int                g_hist[N_ATOMS];
__device__ int                g_row[N_ATOMS + 1];
__device__ int                g_cur[N_ATOMS];
__device__ int                g_part[128];
__device__ int                g_done;
__device__ int                g_flag;
__device__ unsigned int       g_edata[N_EDGES];      /* s:17 | ti:9 | f6:6 */
__device__ float4             g_pos4[N_ATOMS];
__device__ __align__(16)  __half g_traw[NLAYERS * TBL_T * HID];
__device__ __align__(16)  __half g_tbl2[NLAYERS * TBL_T * HID * 2];
__device__ float              g_h[(size_t)N_ATOMS * HID];
__device__ __align__(128) __half g_x[(size_t)N_ATOMS * HID];
__device__ __align__(128) __half g_aggh[(size_t)N_ATOMS * HID];
__device__ float              g_molsum[N_MOL];
__device__ __align__(16) __half g_cf1h[NLAYERS * HID * HID];
__device__ __align__(16) __half g_cf2h[NLAYERS * HID * HID];
__device__ __align__(16) __half g_inth[NLAYERS * HID * HID];

__device__ __forceinline__ float ssp(float v) {
    return fmaxf(v, 0.0f) + log1pf(expf(-fabsf(v))) - LOG2F_;
}

/* --------------- wmma 128x64x64 tile helpers ----------------------------- */
__device__ __forceinline__ void wmma_gemm(const __half* sA, const __half* sB, float* sC) {
    int w = threadIdx.x >> 5;
    wmma::fragment<wmma::accumulator, 16, 16, 16, float> c[4];
#pragma unroll
    for (int n = 0; n < 4; n++) wmma::fill_fragment(c[n], 0.0f);
#pragma unroll
    for (int k = 0; k < 4; k++) {
        wmma::fragment<wmma::matrix_a, 16, 16, 16, __half, wmma::row_major> a;
        wmma::load_matrix_sync(a, sA + (w * 16) * LDA + k * 16, LDA);
#pragma unroll
        for (int n = 0; n < 4; n++) {
            wmma::fragment<wmma::matrix_b, 16, 16, 16, __half, wmma::row_major> b;
            wmma::load_matrix_sync(b, sB + (k * 16) * LDA + n * 16, LDA);
            wmma::mma_sync(c[n], a, b, c[n]);
        }
    }
#pragma unroll
    for (int n = 0; n < 4; n++)
        wmma::store_matrix_sync(sC + (w * 16) * LDC + n * 16, c[n], LDC, wmma::mem_row_major);
}

__device__ __forceinline__ void load_B(__half* sB, const __half* W, int tid) {
    for (int i = tid; i < 64 * 32; i += 256) {
        int row = i >> 5, c2 = i & 31;
        *(unsigned int*)&sB[row * LDA + c2 * 2] = ((const unsigned int*)W)[row * 32 + c2];
    }
}

/* =========== K1: wprep + pos4 repack + table + hist (fused) ============== */
__global__ void __launch_bounds__(256) k1_prep_table_hist(
        const float* __restrict__ cf1, const float* __restrict__ cf2,
        const float* __restrict__ intw,
        const float* __restrict__ w1, const float* __restrict__ b1,
        const float* __restrict__ w2, const float* __restrict__ b2,
        const int* __restrict__ ei, const float* __restrict__ pos) {
    int bid = blockIdx.x;
    int tid = threadIdx.x;

    if (bid < WPREP_BLK) {
        int i = bid * 256 + tid;
        if (i < NLAYERS * HID * HID) {
            g_cf1h[i] = __float2half_rn(cf1[i]);
            g_cf2h[i] = __float2half_rn(cf2[i]);
            g_inth[i] = __float2half_rn(intw[i]);
        }
        return;
    }
    if (bid < WPREP_BLK + POS_BLK) {
        int i = (bid - WPREP_BLK) * 256 + tid;
        if (i < N_ATOMS)
            g_pos4[i] = make_float4(pos[3 * i], pos[3 * i + 1], pos[3 * i + 2], 0.0f);
        return;
    }
    if (bid < WPREP_BLK + POS_BLK + TBL_BLK) {
        __shared__ float W1s[NGAUSS][HID];
        __shared__ float W2s[HID][HID];
        __shared__ float rbfs[TB_TPB][NGAUSS];
        __shared__ float tmps[TB_TPB][HID];
        int tb = bid - WPREP_BLK - POS_BLK;
        int l = tb / (TBL_T / TB_TPB);
        int tbase = (tb % (TBL_T / TB_TPB)) * TB_TPB;

        for (int i = tid; i < NGAUSS * HID; i += 256)
            W1s[i / HID][i % HID] = w1[(size_t)l * NGAUSS * HID + i];
        for (int i = tid; i < HID * HID; i += 256)
            W2s[i >> 6][i & 63] = w2[(size_t)l * HID * HID + i];
        for (int i = tid; i < TB_TPB * NGAUSS; i += 256) {
            int tt = i / NGAUSS, k = i % NGAUSS;
            float d = (float)(tbase + tt) * (DMAX / (float)(TBL_T - 1));
            float off = (float)k * (10.0f / 49.0f);
            float u = d - off;
            const float coeff = -0.5f * (49.0f / 10.0f) * (49.0f / 10.0f);
            rbfs[tt][k] = expf(coeff * u * u);
        }
        __syncthreads();

        for (int i = tid; i < TB_TPB * HID; i += 256) {
            int tt = i >> 6, j = i & 63;
            float acc = b1[l * HID + j];
#pragma unroll
            for (int k = 0; k < NGAUSS; k++) acc = fmaf(rbfs[tt][k], W1s[k][j], acc);
            tmps[tt][j] = ssp(acc);
        }
        __syncthreads();

        for (int i = tid; i < TB_TPB * HID; i += 256) {
            int tt = i >> 6, j = i & 63;
            float acc = b2[l * HID + j];
#pragma unroll
            for (int k = 0; k < HID; k++) acc = fmaf(tmps[tt][k], W2s[k][j], acc);
            float d = (float)(tbase + tt) * (DMAX / (float)(TBL_T - 1));
            float C = 0.5f * (cosf(d * PI_OVER_CUTOFF) + 1.0f);
            g_traw[((size_t)l * TBL_T + tbase + tt) * HID + j] = __float2half_rn(acc * C);
        }
        return;
    }
    int e = (bid - WPREP_BLK - POS_BLK - TBL_BLK) * 256 + tid;
    if (e < N_EDGES) atomicAdd(&g_hist[ei[N_EDGES + e]], 1);
}

/* ====== K2: scanA(+B last block) + pack + dense_x + scanC(spin) ========== */
__global__ void __launch_bounds__(256) k2_scan_pack_densex(const int* __restrict__ z,
                                                           const float* __restrict__ emb) {
    int bid = blockIdx.x;
    int tid = threadIdx.x;

    if (bid < SCAN_BLK) {
        __shared__ int wsum[8];
        __shared__ int s_last;
        int lane = tid & 31, wid = tid >> 5;
        int idx = bid * 1024 + tid * 4;

        int v0 = (idx + 0 < N_ATOMS) ? g_hist[idx + 0] : 0;
        int v1 = (idx + 1 < N_ATOMS) ? g_hist[idx + 1] : 0;
        int v2 = (idx + 2 < N_ATOMS) ? g_hist[idx + 2] : 0;
        int v3 = (idx + 3 < N_ATOMS) ? g_hist[idx + 3] : 0;
        if (idx + 0 < N_ATOMS) g_hist[idx + 0] = 0;
        if (idx + 1 < N_ATOMS) g_hist[idx + 1] = 0;
        if (idx + 2 < N_ATOMS) g_hist[idx + 2] = 0;
        if (idx + 3 < N_ATOMS) g_hist[idx + 3] = 0;

        int s = v0 + v1 + v2 + v3;
        int si = s;
#pragma unroll
        for (int o = 1; o < 32; o <<= 1) {
            int u = __shfl_up_sync(0xffffffffu, si, o);
            if (lane >= o) si += u;
        }
        if (lane == 31) wsum[wid] = si;
        __syncthreads();
        if (wid == 0 && lane < 8) {
            int w = wsum[lane];
#pragma unroll
            for (int o = 1; o < 8; o <<= 1) {
                int u = __shfl_up_sync(0x000000ffu, w, o);
                if (lane >= o) w += u;
            }
            wsum[lane] = w;
        }
        __syncthreads();
        int off = ((wid > 0) ? wsum[wid - 1] : 0) + (si - s);
        if (idx + 0 < N_ATOMS) g_row[idx + 0] = off;
        if (idx + 1 < N_ATOMS) g_row[idx + 1] = off + v0;
        if (idx + 2 < N_ATOMS) g_row[idx + 2] = off + v0 + v1;
        if (idx + 3 < N_ATOMS) g_row[idx + 3] = off + v0 + v1 + v2;
        if (tid == 0) g_part[bid] = wsum[7];

        __threadfence();
        if (tid == 0) s_last = (atomicAdd(&g_done, 1) == SCAN_BLK - 1);
        __syncthreads();
        if (s_last) {
            __threadfence();
            if (tid < 32) {
                int lane2 = tid;
                int i = lane2 * 4;
                int u0 = (i + 0 < SCAN_BLK) ? g_part[i + 0] : 0;
                int u1 = (i + 1 < SCAN_BLK) ? g_part[i + 1] : 0;
                int u2 = (i + 2 < SCAN_BLK) ? g_part[i + 2] : 0;
                int u3 = (i + 3 < SCAN_BLK) ? g_part[i + 3] : 0;
                int ss = u0 + u1 + u2 + u3;
                int ssi = ss;
#pragma unroll
                for (int o = 1; o < 32; o <<= 1) {
                    int u = __shfl_up_sync(0xffffffffu, ssi, o);
                    if (lane2 >= o) ssi += u;
                }
                int excl = ssi - ss;
                if (i + 0 < SCAN_BLK) g_part[i + 0] = excl;
                if (i + 1 < SCAN_BLK) g_part[i + 1] = excl + u0;
                if (i + 2 < SCAN_BLK) g_part[i + 2] = excl + u0 + u1;
                if (i + 3 < SCAN_BLK) g_part[i + 3] = excl + u0 + u1 + u2;
                if (lane2 == 31) g_row[N_ATOMS] = ssi;
                __syncwarp();
                if (lane2 == 0) {
                    g_done = 0;
                    __threadfence();
                    g_flag = 1;
                }
            }
        }
        return;
    }
    if (bid < SCAN_BLK + PACK_BLK) {
        /* pack raw -> interleaved (a, delta/64) */
        int i = (bid - SCAN_BLK) * 256 + tid;
        if (i >= NLAYERS * TBL_T * 32) return;
        int c2 = i & 31;
        int t  = (i >> 5) & (TBL_T - 1);
        int l  = i / (TBL_T * 32);
        const __half2* raw = (const __half2*)g_traw;
        __half2 a = raw[((size_t)l * TBL_T + t) * 32 + c2];
        int tn = (t + 1 < TBL_T) ? t + 1 : t;
        __half2 b = raw[((size_t)l * TBL_T + tn) * 32 + c2];
        __half2 d = __hmul2(__hsub2(b, a), __float2half2_rn(1.0f / 64.0f));
        __half2* dst = (__half2*)g_tbl2;
        dst[(((size_t)l * TBL_T + t) * 32 + c2) * 2 + 0] = a;
        dst[(((size_t)l * TBL_T + t) * 32 + c2) * 2 + 1] = d;
        return;
    }
    if (bid < SCAN_BLK + PACK_BLK + DX_BLK) {
        extern __shared__ char sm[];
        __half* sA = (__half*)(sm + SM_A_OFF);
        __half* sB = (__half*)(sm + SM_B_OFF);
        float*  sC = (float*)(sm + SM_C_OFF);
        size_t r0 = (size_t)(bid - SCAN_BLK - PACK_BLK) * 128;

        for (int i = tid; i < 128 * 64; i += 256) {
            int row = i >> 6, col = i & 63;
            size_t gr = r0 + row;
            float v = 0.0f;
            if (gr < N_ATOMS) {
                v = emb[(size_t)z[gr] * HID + col];
                g_h[gr * HID + col] = v;
            }
            sA[row * LDA + col] = __float2half_rn(v);
        }
        load_B(sB, g_cf1h, tid);
        __syncthreads();
        wmma_gemm(sA, sB, sC);
        __syncthreads();
        for (int i = tid; i < 128 * 32; i += 256) {
            int row = i >> 5, c2 = i & 31;
            size_t gr = r0 + row;
            if (gr < N_ATOMS) {
                __half2 hv = __floats2half2_rn(sC[row * LDC + c2 * 2], sC[row * LDC + c2 * 2 + 1]);
                *(__half2*)(g_x + gr * HID + c2 * 2) = hv;
            }
        }
        return;
    }
    if (tid == 0) {
        while (!*((volatile int*)&g_flag)) __nanosleep(64);
    }
    __syncthreads();
    __threadfence();
    int i = (bid - SCAN_BLK - PACK_BLK - DX_BLK) * 256 + tid;
    if (i >= N_ATOMS) return;
    int v = g_row[i] + g_part[i >> 10];
    g_row[i] = v;
    g_cur[i] = v;
}

/* =================== K3: scatter (32-bit records) ======================== */
__global__ void scatter_kernel(const int* __restrict__ ei) {
    int e = blockIdx.x * blockDim.x + threadIdx.x;
    if (e == 0) g_flag = 0;
    if (e >= N_EDGES) return;
    int s = ei[e];
    int t = ei[N_EDGES + e];
    float4 ps = g_pos4[s];
    float4 pt = g_pos4[t];
    float dx = ps.x - pt.x, dy = ps.y - pt.y, dz = ps.z - pt.z;
    float d = sqrtf(dx * dx + dy * dy + dz * dz);
    unsigned ti6 = min((unsigned)(d * TBL_SCALE64), (unsigned)TI6_MAX);
    int p = atomicAdd(&g_cur[t], 1);
    g_edata[p] = ((unsigned)s << 15) | ti6;
}

/* ====== K4: message + segment-sum (PROFILED SLOT) ======================== */
__global__ void __launch_bounds__(1024, 1) aggregate_kernel(int layer) {
    extern __shared__ __align__(16) char s_raw[];
    {
        const uint4* src = (const uint4*)(g_tbl2 + (size_t)layer * TBL_T * HID * 2);
        uint4* dst = (uint4*)s_raw;
        for (int i = threadIdx.x; i < TBL2_BYTES / 16; i += 1024) dst[i] = src[i];
    }
    __syncthreads();

    int lane = threadIdx.x & 31;
    int wib  = threadIdx.x >> 5;
    int lane8 = lane * 8;
    const char* s_tab = s_raw;
    const __half2* xlane = (const __half2*)g_x + lane;

    for (int node = blockIdx.x * 32 + wib; node < N_ATOMS; node += gridDim.x * 32) {
        int beg = g_row[node];
        int end = g_row[node + 1];
        float accx = 0.0f, accy = 0.0f;

        for (int base = beg; base < end; base += 32) {
            int cnt = min(32, end - base);
            unsigned pk = (lane < cnt) ? __ldcs(&g_edata[base + lane]) : 0u;

            int j = 0;
            for (; j + 8 <= cnt; j += 8) {
                unsigned p[8];
#pragma unroll
                for (int k = 0; k < 8; k++)
                    p[k] = __shfl_sync(0xffffffffu, pk, j + k);
                __half2 xv[8];
#pragma unroll
                for (int k = 0; k < 8; k++)
                    xv[k] = xlane[(p[k] >> 15) * 32u];
                __half2 m[8];
#pragma unroll
                for (int k = 0; k < 8; k++) {
                    uint2 ad = *(const uint2*)(s_tab + (((p[k] & 0x7FC0u) << 2) + lane8));
                    __half f1 = __ushort2half_rn((unsigned short)(p[k] & 63u));
                    m[k] = __hmul2(__hfma2(__half2half2(f1), *(__half2*)&ad.y, *(__half2*)&ad.x), xv[k]);
                }
                __half2 t1 = __hadd2(__hadd2(m[0], m[1]), __hadd2(m[2], m[3]));
                __half2 t2 = __hadd2(__hadd2(m[4], m[5]), __hadd2(m[6], m[7]));
                float2 f1s = __half22float2(t1);
                float2 f2s = __half22float2(t2);
                accx += f1s.x + f2s.x;
                accy += f1s.y + f2s.y;
            }
            for (; j < cnt; j++) {
                unsigned p = __shfl_sync(0xffffffffu, pk, j);
                uint2 ad = *(const uint2*)(s_tab + (((p & 0x7FC0u) << 2) + lane8));
                __half f1 = __ushort2half_rn((unsigned short)(p & 63u));
                __half2 xv = xlane[(p >> 15) * 32u];
                float2 mf = __half22float2(
                    __hmul2(__hfma2(__half2half2(f1), *(__half2*)&ad.y, *(__half2*)&ad.x), xv));
                accx += mf.x;
                accy += mf.y;
            }
        }
        *(__half2*)(g_aggh + (size_t)node * HID + lane * 2) = __floats2half2_rn(accx, accy);
    }
}

/* --- h += ssp(agg@W1+b1)@W2+b2 ; x = h_new@W3 (all tensor-core) ---------- */
__global__ void __launch_bounds__(256) dense_post_w(int l, int fuse_next,
                                                    const float* __restrict__ b1,
                                                    const float* __restrict__ b2) {
    extern __shared__ char sm[];
    __half* sA = (__half*)(sm + SM_A_OFF);
    __half* sB = (__half*)(sm + SM_B_OFF);
    float*  sC = (float*)(sm + SM_C_OFF);
    int tid = threadIdx.x;
    size_t r0 = (size_t)blockIdx.x * 128;

    const __half* W1 = g_cf2h + (size_t)l * HID * HID;
    const __half* W2 = g_inth + (size_t)l * HID * HID;
    const __half* W3 = g_cf1h + (size_t)(l + 1 < NLAYERS ? l + 1 : 0) * HID * HID;

    for (int i = tid; i < 128 * 32; i += 256) {
        int row = i >> 5, c2 = i & 31;
        unsigned int v = 0;
        if (r0 + row < N_ATOMS)
            v = ((const unsigned int*)g_aggh)[(r0 + row) * 32 + c2];
        *(unsigned int*)&sA[row * LDA + c2 * 2] = v;
    }
    load_B(sB, W1, tid);
    __syncthreads();
    wmma_gemm(sA, sB, sC);
    __syncthreads();

    for (int i = tid; i < 128 * 64; i += 256) {
        int row = i >> 6, col = i & 63;
        float v = ssp(sC[row * LDC + col] + __ldg(&b1[col]));
        sA[row * LDA + col] = __float2half_rn(v);
    }
    load_B(sB, W2, tid);
    __syncthreads();
    wmma_gemm(sA, sB, sC);
    __syncthreads();

    for (int i = tid; i < 128 * 64; i += 256) {
        int row = i >> 6, col = i & 63;
        size_t gr = r0 + row;
        float v = 0.0f;
        if (gr < N_ATOMS) {
            v = g_h[gr * HID + col] + sC[row * LDC + col] + __ldg(&b2[col]);
            g_h[gr * HID + col] = v;
        }
        sA[row * LDA + col] = __float2half_rn(v);
    }
    if (!fuse_next) return;

    load_B(sB, W3, tid);
    __syncthreads();
    wmma_gemm(sA, sB, sC);
    __syncthreads();
    for (int i = tid; i < 128 * 32; i += 256) {
        int row = i >> 5, c2 = i & 31;
        size_t gr = r0 + row;
        if (gr < N_ATOMS) {
            __half2 hv = __floats2half2_rn(sC[row * LDC + c2 * 2], sC[row * LDC + c2 * 2 + 1]);
            *(__half2*)(g_x + gr * HID + c2 * 2) = hv;
        }
    }
}

/* --------------- readout: per-atom MLP (64->32->1) + molecule sum -------- */
__global__ void readout_kernel(const int* __restrict__ batch,
                               const float* __restrict__ w1, const float* __restrict__ b1,
                               const float* __restrict__ w2, const float* __restrict__ b2) {
    int warp = (blockIdx.x * blockDim.x + threadIdx.x) >> 5;
    int lane = threadIdx.x & 31;
    if (warp >= N_ATOMS) return;

    float h0 = g_h[(size_t)warp * HID + lane];
    float h1 = g_h[(size_t)warp * HID + 32 + lane];

    float acc = b1[lane];
#pragma unroll
    for (int k = 0; k < 32; k++) {
        float hk = __shfl_sync(0xffffffffu, h0, k);
        acc = fmaf(hk, w1[k * 32 + lane], acc);
    }
#pragma unroll
    for (int k = 0; k < 32; k++) {
        float hk = __shfl_sync(0xffffffffu, h1, k);
        acc = fmaf(hk, w1[(32 + k) * 32 + lane], acc);
    }
    float t = ssp(acc) * w2[lane];
#pragma unroll
    for (int o = 16; o > 0; o >>= 1) t += __shfl_xor_sync(0xffffffffu, t, o);
    if (lane == 0) atomicAdd(&g_molsum[batch[warp]], t + b2[0]);
}

/* ------- out[g] = molsum[g]*fin_w + fin_b ; self-restore molsum ---------- */
__global__ void final_kernel(const float* __restrict__ fw, const float* __restrict__ fb,
                             float* __restrict__ out) {
    int g = blockIdx.x * blockDim.x + threadIdx.x;
    if (g < N_MOL) {
        float v = g_molsum[g];
        out[g] = v * fw[0] + fb[0];
        g_molsum[g] = 0.0f;
    }
}

/* ========================================================================= */
extern "C" void kernel_launch(void* const* d_in, const int* in_sizes, int n_in,
                              void* d_out, int out_size) {
    const int*   z      = (const int*)d_in[0];
    const float* pos    = (const float*)d_in[1];
    const int*   batch  = (const int*)d_in[2];
    const int*   ei     = (const int*)d_in[3];
    const float* emb    = (const float*)d_in[4];
    const float* out_w1 = (const float*)d_in[5];
    const float* out_b1 = (const float*)d_in[6];
    const float* out_w2 = (const float*)d_in[7];
    const float* out_b2 = (const float*)d_in[8];
    const float* fin_w  = (const float*)d_in[9];
    const float* fin_b  = (const float*)d_in[10];
    const float* mlp_w1 = (const float*)d_in[11];
    const float* mlp_b1 = (const float*)d_in[12];
    const float* mlp_w2 = (const float*)d_in[13];
    const float* mlp_b2 = (const float*)d_in[14];
    const float* cf1    = (const float*)d_in[15];
    const float* cf2    = (const float*)d_in[16];
    const float* cf2b   = (const float*)d_in[17];
    const float* intw   = (const float*)d_in[18];
    const float* intb   = (const float*)d_in[19];

    (void)in_sizes; (void)n_in; (void)out_size;

    cudaFuncSetAttribute(aggregate_kernel,
                         cudaFuncAttributeMaxDynamicSharedMemorySize, TBL2_BYTES);
    cudaFuncSetAttribute(k2_scan_pack_densex,
                         cudaFuncAttributeMaxDynamicSharedMemorySize, SM_TOTAL);
    cudaFuncSetAttribute(dense_post_w,
                         cudaFuncAttributeMaxDynamicSharedMemorySize, SM_TOTAL);

    k1_prep_table_hist<<<WPREP_BLK + POS_BLK + TBL_BLK + HIST_BLK, 256>>>(
        cf1, cf2, intw, mlp_w1, mlp_b1, mlp_w2, mlp_b2, ei, pos);
    k2_scan_pack_densex<<<SCAN_BLK + PACK_BLK + DX_BLK + SCANC_BLK, 256, SM_TOTAL>>>(z, emb);
    scatter_kernel<<<(N_EDGES + 255) / 256, 256>>>(ei);

    for (int l = 0; l < NLAYERS; l++) {
        aggregate_kernel<<<AGG_BLOCKS, 1024, TBL2_BYTES>>>(l);
        dense_post_w<<<DX_BLK, 256, SM_TOTAL>>>(l, (l + 1 < NLAYERS),
                                                cf2b + (size_t)l * HID,
                                                intb + (size_t)l * HID);
    }

    int warp_blocks = (N_ATOMS * 32 + 255) / 256;
    readout_kernel<<<warp_blocks, 256>>>(batch, out_w1, out_b1, out_w2, out_b2);
    final_kernel<<<(N_MOL + 255) / 256, 256>>>(fin_w, fin_b, (float*)d_out);
}